// round 1
// baseline (speedup 1.0000x reference)
#include <cuda_runtime.h>
#include <cuda_bf16.h>
#include <cstdint>

#define NN 50000
#define EE 600000
#define HH 128
#define LL 4
#define GG 256
#define CC 10
#define BN_EPS 1e-5f

// -------- device scratch (no allocations allowed) --------
__device__ float d_h[NN * HH];      // current node features
__device__ float d_z[NN * HH];      // agg buffer / z2 buffer
__device__ float d_y[NN * HH];      // GEMM1 output
__device__ float d_pool[GG * LL * HH];
__device__ float d_statsA[4 * HH];  // [0:128) sum, [128:256) sumsq, [256:384) mu, [384:512) rsigma
__device__ float d_statsB[4 * HH];
__device__ int   d_start[GG + 1];

// -------- graph boundaries from sorted batch --------
__global__ void k_bounds(const int* __restrict__ batch) {
    int n = blockIdx.x * blockDim.x + threadIdx.x;
    if (n >= NN) return;
    int g = batch[n];
    if (n == 0) {
        for (int gg = 0; gg <= g; ++gg) d_start[gg] = 0;
    } else {
        int gp = batch[n - 1];
        for (int gg = gp + 1; gg <= g; ++gg) d_start[gg] = n;
    }
    if (n == NN - 1) {
        for (int gg = g + 1; gg <= GG; ++gg) d_start[gg] = NN;
    }
}

__global__ void k_zero_stats() {
    int t = threadIdx.x;           // 256 threads zero sum+sumsq of both
    d_statsA[t] = 0.f;
    d_statsB[t] = 0.f;
}

// z = (1+eps[layer]) * h
__global__ void k_init_z(const float* __restrict__ hin, const float* __restrict__ eps, int layer) {
    int t = blockIdx.x * blockDim.x + threadIdx.x;
    if (t >= NN * 32) return;
    float s = 1.f + eps[layer];
    float4 v = ((const float4*)hin)[t];
    v.x *= s; v.y *= s; v.z *= s; v.w *= s;
    ((float4*)d_z)[t] = v;
}

// z[dst] += h[src] over all edges (32 threads/edge, float4 each)
__global__ void k_scatter(const float* __restrict__ hin,
                          const int* __restrict__ src, const int* __restrict__ dst) {
    int t = blockIdx.x * blockDim.x + threadIdx.x;
    if (t >= EE * 32) return;
    int e = t >> 5, cg = t & 31;
    int s = src[e], d = dst[e];
    float4 v = ((const float4*)hin)[s * 32 + cg];
    float* zp = d_z + (size_t)d * HH + cg * 4;
    atomicAdd(zp + 0, v.x);
    atomicAdd(zp + 1, v.y);
    atomicAdd(zp + 2, v.z);
    atomicAdd(zp + 3, v.w);
}

// -------- tiled SGEMM: out[N,128] = f(A)[N,128] @ W[128,128] + bias --------
// BN_IN: apply (a-mu)*rs*g+b, relu to A elements (stats read from d_statsA)
// Always accumulates per-channel sum/sumsq of the output into outstats.
#define BM 64
#define BK 16
template <bool BN_IN>
__global__ __launch_bounds__(256) void k_gemm(
    const float* __restrict__ A, const float* __restrict__ W,
    const float* __restrict__ bias,
    const float* __restrict__ bng, const float* __restrict__ bnb,
    float* __restrict__ out, float* __restrict__ outstats) {

    __shared__ float As[BK][BM];
    __shared__ float Bs[BK][HH];
    __shared__ float s_sum[HH];
    __shared__ float s_sq[HH];

    int tid = threadIdx.x;
    int tx = tid & 15;    // column group (8 cols)
    int ty = tid >> 4;    // row group (4 rows)
    int row0 = blockIdx.x * BM;

    if (tid < HH) { s_sum[tid] = 0.f; s_sq[tid] = 0.f; }

    float acc[4][8];
#pragma unroll
    for (int i = 0; i < 4; i++)
#pragma unroll
        for (int j = 0; j < 8; j++) acc[i][j] = 0.f;

    int a_row = tid >> 2;          // 0..63
    int a_k4  = (tid & 3) * 4;     // 0,4,8,12
    int b_r   = tid >> 5;          // 0..7
    int b_c   = (tid & 31) * 4;    // 0..124

    const float* mu = d_statsA + 256;
    const float* rs = d_statsA + 384;

    for (int kt = 0; kt < HH; kt += BK) {
        float4 av;
        int gr = row0 + a_row;
        if (gr < NN) av = *(const float4*)(A + (size_t)gr * HH + kt + a_k4);
        else         av = make_float4(0.f, 0.f, 0.f, 0.f);
        if (BN_IN) {
            int kg = kt + a_k4;
            av.x = fmaxf((av.x - mu[kg + 0]) * rs[kg + 0] * bng[kg + 0] + bnb[kg + 0], 0.f);
            av.y = fmaxf((av.y - mu[kg + 1]) * rs[kg + 1] * bng[kg + 1] + bnb[kg + 1], 0.f);
            av.z = fmaxf((av.z - mu[kg + 2]) * rs[kg + 2] * bng[kg + 2] + bnb[kg + 2], 0.f);
            av.w = fmaxf((av.w - mu[kg + 3]) * rs[kg + 3] * bng[kg + 3] + bnb[kg + 3], 0.f);
        }
        float4 bv0 = *(const float4*)(W + (size_t)(kt + b_r) * HH + b_c);
        float4 bv1 = *(const float4*)(W + (size_t)(kt + b_r + 8) * HH + b_c);

        __syncthreads();
        As[a_k4 + 0][a_row] = av.x;
        As[a_k4 + 1][a_row] = av.y;
        As[a_k4 + 2][a_row] = av.z;
        As[a_k4 + 3][a_row] = av.w;
        *(float4*)&Bs[b_r][b_c]     = bv0;
        *(float4*)&Bs[b_r + 8][b_c] = bv1;
        __syncthreads();

#pragma unroll
        for (int k = 0; k < BK; k++) {
            float ar[4], br[8];
#pragma unroll
            for (int i = 0; i < 4; i++) ar[i] = As[k][ty * 4 + i];
            *(float4*)&br[0] = *(const float4*)&Bs[k][tx * 8];
            *(float4*)&br[4] = *(const float4*)&Bs[k][tx * 8 + 4];
#pragma unroll
            for (int i = 0; i < 4; i++)
#pragma unroll
                for (int j = 0; j < 8; j++) acc[i][j] += ar[i] * br[j];
        }
    }

    // epilogue: bias + store + channel stats
#pragma unroll
    for (int j = 0; j < 8; j++) {
        int c = tx * 8 + j;
        float bcol = bias[c];
        float psum = 0.f, psq = 0.f;
#pragma unroll
        for (int i = 0; i < 4; i++) {
            int gr = row0 + ty * 4 + i;
            if (gr < NN) {
                float v = acc[i][j] + bcol;
                out[(size_t)gr * HH + c] = v;
                psum += v;
                psq  += v * v;
            }
        }
        atomicAdd(&s_sum[c], psum);
        atomicAdd(&s_sq[c], psq);
    }
    __syncthreads();
    if (tid < HH) {
        atomicAdd(&outstats[tid], s_sum[tid]);
        atomicAdd(&outstats[HH + tid], s_sq[tid]);
    }
}

__global__ void k_finalize(float* st) {
    int t = threadIdx.x;   // 128
    float s = st[t], q = st[HH + t];
    float mu = s * (1.f / NN);
    float var = q * (1.f / NN) - mu * mu;
    st[256 + t] = mu;
    st[384 + t] = rsqrtf(var + BN_EPS);
}

// h = relu(bn2(z2)) ; stats from d_statsB
__global__ void k_bn_relu(const float* __restrict__ z,
                          const float* __restrict__ g2, const float* __restrict__ b2) {
    int t = blockIdx.x * blockDim.x + threadIdx.x;
    if (t >= NN * 32) return;
    int c = (t & 31) * 4;
    const float* mu = d_statsB + 256;
    const float* rs = d_statsB + 384;
    float4 v = ((const float4*)z)[t];
    v.x = fmaxf((v.x - mu[c + 0]) * rs[c + 0] * g2[c + 0] + b2[c + 0], 0.f);
    v.y = fmaxf((v.y - mu[c + 1]) * rs[c + 1] * g2[c + 1] + b2[c + 1], 0.f);
    v.z = fmaxf((v.z - mu[c + 2]) * rs[c + 2] * g2[c + 2] + b2[c + 2], 0.f);
    v.w = fmaxf((v.w - mu[c + 3]) * rs[c + 3] * g2[c + 3] + b2[c + 3], 0.f);
    ((float4*)d_h)[t] = v;
}

// per-graph pooled sum of d_h into d_pool[g][layer*128 + c]  (no atomics; batch sorted)
__global__ void k_pool(int layer) {
    int g = blockIdx.x;
    int c = threadIdx.x;   // 128
    int s = d_start[g], e = d_start[g + 1];
    float a0 = 0.f, a1 = 0.f, a2 = 0.f, a3 = 0.f;
    int n = s;
    for (; n + 3 < e; n += 4) {
        a0 += d_h[(size_t)(n + 0) * HH + c];
        a1 += d_h[(size_t)(n + 1) * HH + c];
        a2 += d_h[(size_t)(n + 2) * HH + c];
        a3 += d_h[(size_t)(n + 3) * HH + c];
    }
    for (; n < e; ++n) a0 += d_h[(size_t)n * HH + c];
    d_pool[(size_t)g * (LL * HH) + layer * HH + c] = (a0 + a1) + (a2 + a3);
}

// out[g] = relu(pool[g] @ fc1 + b1) @ fc2 + b2
__global__ void k_head(const float* __restrict__ fc1w, const float* __restrict__ fc1b,
                       const float* __restrict__ fc2w, const float* __restrict__ fc2b,
                       float* __restrict__ out) {
    __shared__ float sp[LL * HH];
    __shared__ float t1[HH];
    int g = blockIdx.x, t = threadIdx.x;   // 128 threads
    for (int k = t; k < LL * HH; k += HH) sp[k] = d_pool[(size_t)g * (LL * HH) + k];
    __syncthreads();
    float acc = fc1b[t];
#pragma unroll 8
    for (int k = 0; k < LL * HH; k++) acc += sp[k] * fc1w[(size_t)k * HH + t];
    t1[t] = fmaxf(acc, 0.f);
    __syncthreads();
    if (t < CC) {
        float a = fc2b[t];
#pragma unroll 8
        for (int j = 0; j < HH; j++) a += t1[j] * fc2w[j * CC + t];
        out[g * CC + t] = a;
    }
}

extern "C" void kernel_launch(void* const* d_in, const int* in_sizes, int n_in,
                              void* d_out, int out_size) {
    const float* x     = (const float*)d_in[0];
    const int*   ei    = (const int*)d_in[1];
    const int*   batch = (const int*)d_in[2];
    const float* W1    = (const float*)d_in[3];
    const float* b1    = (const float*)d_in[4];
    const float* g1    = (const float*)d_in[5];
    const float* bt1   = (const float*)d_in[6];
    const float* W2    = (const float*)d_in[7];
    const float* b2    = (const float*)d_in[8];
    const float* g2    = (const float*)d_in[9];
    const float* bt2   = (const float*)d_in[10];
    const float* eps   = (const float*)d_in[11];
    const float* fc1w  = (const float*)d_in[12];
    const float* fc1b  = (const float*)d_in[13];
    const float* fc2w  = (const float*)d_in[14];
    const float* fc2b  = (const float*)d_in[15];
    float* out = (float*)d_out;

    const int* src = ei;
    const int* dst = ei + EE;

    float *hbuf, *zbuf, *ybuf, *stA, *stB;
    cudaGetSymbolAddress((void**)&hbuf, d_h);
    cudaGetSymbolAddress((void**)&zbuf, d_z);
    cudaGetSymbolAddress((void**)&ybuf, d_y);
    cudaGetSymbolAddress((void**)&stA, d_statsA);
    cudaGetSymbolAddress((void**)&stB, d_statsB);

    const int elem_blocks = (NN * 32 + 255) / 256;           // 6250
    const int scat_blocks = (EE * 32 + 255) / 256;           // 75000
    const int gemm_blocks = (NN + BM - 1) / BM;              // 782

    k_bounds<<<(NN + 255) / 256, 256>>>(batch);

    for (int i = 0; i < LL; i++) {
        const float* hin = (i == 0) ? x : hbuf;
        k_zero_stats<<<1, 256>>>();
        k_init_z<<<elem_blocks, 256>>>(hin, eps, i);
        k_scatter<<<scat_blocks, 256>>>(hin, src, dst);
        // y = z @ W1[i] + b1[i]; stats -> A
        k_gemm<false><<<gemm_blocks, 256>>>(zbuf, W1 + (size_t)i * HH * HH,
                                            b1 + i * HH, nullptr, nullptr,
                                            ybuf, stA);
        k_finalize<<<1, HH>>>(stA);
        // z2 = relu(bn1(y)) @ W2[i] + b2[i]; stats -> B
        k_gemm<true><<<gemm_blocks, 256>>>(ybuf, W2 + (size_t)i * HH * HH,
                                           b2 + i * HH, g1 + i * HH, bt1 + i * HH,
                                           zbuf, stB);
        k_finalize<<<1, HH>>>(stB);
        k_bn_relu<<<elem_blocks, 256>>>(zbuf, g2 + i * HH, bt2 + i * HH);
        k_pool<<<GG, HH>>>(i);
    }

    k_head<<<GG, HH>>>(fc1w, fc1b, fc2w, fc2b, out);
}

// round 2
// speedup vs baseline: 1.4452x; 1.4452x over previous
#include <cuda_runtime.h>
#include <cuda_bf16.h>
#include <cstdint>

#define NN 50000
#define EE 600000
#define HH 128
#define LL 4
#define GG 256
#define CC 10
#define BN_EPS 1e-5f

// -------- device scratch (no allocations allowed) --------
__device__ float d_h[NN * HH];      // current node features
__device__ float d_z[NN * HH];      // agg result / z2 buffer
__device__ float d_y[NN * HH];      // GEMM1 output
__device__ float d_pool[GG * LL * HH];
__device__ float d_statsA[4 * HH];  // [0:128) sum, [128:256) sumsq, [256:384) mu, [384:512) rsigma
__device__ float d_statsB[4 * HH];
__device__ int   d_start[GG + 1];
// CSR (dst-sorted adjacency)
__device__ int   d_cnt[NN];
__device__ int   d_cur[NN];
__device__ int   d_rowptr[NN + 1];
__device__ int   d_col[EE];

// -------- graph boundaries from sorted batch --------
__global__ void k_bounds(const int* __restrict__ batch) {
    int n = blockIdx.x * blockDim.x + threadIdx.x;
    if (n >= NN) return;
    int g = batch[n];
    if (n == 0) {
        for (int gg = 0; gg <= g; ++gg) d_start[gg] = 0;
    } else {
        int gp = batch[n - 1];
        for (int gg = gp + 1; gg <= g; ++gg) d_start[gg] = n;
    }
    if (n == NN - 1) {
        for (int gg = g + 1; gg <= GG; ++gg) d_start[gg] = NN;
    }
}

// -------- CSR build --------
__global__ void k_zero_cnt() {
    int n = blockIdx.x * blockDim.x + threadIdx.x;
    if (n < NN) { d_cnt[n] = 0; d_cur[n] = 0; }
}

__global__ void k_hist(const int* __restrict__ dst) {
    int e = blockIdx.x * blockDim.x + threadIdx.x;
    if (e < EE) atomicAdd(&d_cnt[dst[e]], 1);
}

#define SCAN_T 1024
#define SCAN_CHUNK ((NN + SCAN_T - 1) / SCAN_T)
__global__ void k_scan() {
    __shared__ int sp[SCAN_T];
    int t = threadIdx.x;
    int lo = t * SCAN_CHUNK;
    int hi = min(lo + SCAN_CHUNK, NN);
    int s = 0;
    for (int i = lo; i < hi; ++i) s += d_cnt[i];
    sp[t] = s;
    __syncthreads();
    for (int off = 1; off < SCAN_T; off <<= 1) {
        int v = 0;
        if (t >= off) v = sp[t - off];
        __syncthreads();
        if (t >= off) sp[t] += v;
        __syncthreads();
    }
    int run = (t == 0) ? 0 : sp[t - 1];
    for (int i = lo; i < hi; ++i) { d_rowptr[i] = run; run += d_cnt[i]; }
    if (t == SCAN_T - 1) d_rowptr[NN] = sp[SCAN_T - 1];
}

__global__ void k_fill(const int* __restrict__ src, const int* __restrict__ dst) {
    int e = blockIdx.x * blockDim.x + threadIdx.x;
    if (e >= EE) return;
    int d = dst[e];
    int pos = atomicAdd(&d_cur[d], 1);
    d_col[d_rowptr[d] + pos] = src[e];
}

__global__ void k_zero_stats() {
    int t = threadIdx.x;           // 256 threads zero sum+sumsq of both
    d_statsA[t] = 0.f;
    d_statsB[t] = 0.f;
}

// -------- gather aggregation: z[n] = (1+eps)*h[n] + sum_{s in adj(n)} h[s] --------
// one warp per node, lane owns one float4 column slice
__global__ __launch_bounds__(256) void k_agg(const float* __restrict__ hin,
                                             const float* __restrict__ eps, int layer) {
    int t = blockIdx.x * blockDim.x + threadIdx.x;
    int n = t >> 5;
    int l = t & 31;
    if (n >= NN) return;
    float s = 1.f + __ldg(&eps[layer]);
    const float4* h4 = (const float4*)hin;
    float4 v = h4[(size_t)n * 32 + l];
    float ax = v.x * s, ay = v.y * s, az = v.z * s, aw = v.w * s;
    int p0 = d_rowptr[n], p1 = d_rowptr[n + 1];
    for (int p = p0; p < p1; ++p) {
        int sn = d_col[p];
        float4 u = h4[(size_t)sn * 32 + l];
        ax += u.x; ay += u.y; az += u.z; aw += u.w;
    }
    ((float4*)d_z)[(size_t)n * 32 + l] = make_float4(ax, ay, az, aw);
}

// -------- tiled SGEMM: out[N,128] = f(A)[N,128] @ W[128,128] + bias --------
// BN_IN: apply (a-mu)*rs*g+b, relu to A elements (stats from d_statsA)
// Accumulates per-channel sum/sumsq of output into outstats.
#define BM 128
#define BK 8
template <bool BN_IN>
__global__ __launch_bounds__(256) void k_gemm(
    const float* __restrict__ A, const float* __restrict__ W,
    const float* __restrict__ bias,
    const float* __restrict__ bng, const float* __restrict__ bnb,
    float* __restrict__ out, float* __restrict__ outstats) {

    __shared__ float As[2][BK][BM];
    __shared__ float Bs[2][BK][HH];
    __shared__ float s_sum[HH];
    __shared__ float s_sq[HH];

    int tid = threadIdx.x;
    int tx = tid & 15;     // col group (8 cols)
    int ty = tid >> 4;     // row group (8 rows)
    int row0 = blockIdx.x * BM;

    if (tid < HH) { s_sum[tid] = 0.f; s_sq[tid] = 0.f; }

    // loader mapping
    int a_row = tid >> 1;          // 0..127
    int a_k   = (tid & 1) * 4;     // 0 or 4
    int b_r   = tid >> 5;          // 0..7
    int b_c   = (tid & 31) * 4;    // 0..124

    const float* mu = d_statsA + 256;
    const float* rs = d_statsA + 384;

    float acc[8][8];
#pragma unroll
    for (int i = 0; i < 8; i++)
#pragma unroll
        for (int j = 0; j < 8; j++) acc[i][j] = 0.f;

    auto loadA = [&](int kt) -> float4 {
        int gr = row0 + a_row;
        float4 av = make_float4(0.f, 0.f, 0.f, 0.f);
        if (gr < NN) av = *(const float4*)(A + (size_t)gr * HH + kt + a_k);
        if (BN_IN) {
            int kg = kt + a_k;
            av.x = fmaxf((av.x - mu[kg + 0]) * rs[kg + 0] * bng[kg + 0] + bnb[kg + 0], 0.f);
            av.y = fmaxf((av.y - mu[kg + 1]) * rs[kg + 1] * bng[kg + 1] + bnb[kg + 1], 0.f);
            av.z = fmaxf((av.z - mu[kg + 2]) * rs[kg + 2] * bng[kg + 2] + bnb[kg + 2], 0.f);
            av.w = fmaxf((av.w - mu[kg + 3]) * rs[kg + 3] * bng[kg + 3] + bnb[kg + 3], 0.f);
        }
        return av;
    };

    // prologue: tile 0 into buffer 0
    {
        float4 av = loadA(0);
        float4 bv = *(const float4*)(W + (size_t)b_r * HH + b_c);
        As[0][a_k + 0][a_row] = av.x;
        As[0][a_k + 1][a_row] = av.y;
        As[0][a_k + 2][a_row] = av.z;
        As[0][a_k + 3][a_row] = av.w;
        *(float4*)&Bs[0][b_r][b_c] = bv;
    }
    __syncthreads();

    const int NIT = HH / BK;   // 16
    for (int it = 0; it < NIT; ++it) {
        int cur = it & 1, nxt = cur ^ 1;
        float4 av, bv;
        if (it + 1 < NIT) {
            int kt = (it + 1) * BK;
            av = loadA(kt);
            bv = *(const float4*)(W + (size_t)(kt + b_r) * HH + b_c);
        }

#pragma unroll
        for (int k = 0; k < BK; k++) {
            float ar[8], br[8];
            *(float4*)&ar[0] = *(const float4*)&As[cur][k][ty * 8];
            *(float4*)&ar[4] = *(const float4*)&As[cur][k][ty * 8 + 4];
            *(float4*)&br[0] = *(const float4*)&Bs[cur][k][tx * 8];
            *(float4*)&br[4] = *(const float4*)&Bs[cur][k][tx * 8 + 4];
#pragma unroll
            for (int i = 0; i < 8; i++)
#pragma unroll
                for (int j = 0; j < 8; j++) acc[i][j] += ar[i] * br[j];
        }

        if (it + 1 < NIT) {
            As[nxt][a_k + 0][a_row] = av.x;
            As[nxt][a_k + 1][a_row] = av.y;
            As[nxt][a_k + 2][a_row] = av.z;
            As[nxt][a_k + 3][a_row] = av.w;
            *(float4*)&Bs[nxt][b_r][b_c] = bv;
        }
        __syncthreads();
    }

    // epilogue: bias + store + channel stats
#pragma unroll
    for (int j = 0; j < 8; j++) {
        int c = tx * 8 + j;
        float bcol = bias[c];
        float psum = 0.f, psq = 0.f;
#pragma unroll
        for (int i = 0; i < 8; i++) {
            int gr = row0 + ty * 8 + i;
            if (gr < NN) {
                float v = acc[i][j] + bcol;
                out[(size_t)gr * HH + c] = v;
                psum += v;
                psq  += v * v;
            }
        }
        atomicAdd(&s_sum[c], psum);
        atomicAdd(&s_sq[c], psq);
    }
    __syncthreads();
    if (tid < HH) {
        atomicAdd(&outstats[tid], s_sum[tid]);
        atomicAdd(&outstats[HH + tid], s_sq[tid]);
    }
}

__global__ void k_finalize(float* st) {
    int t = threadIdx.x;   // 128
    float s = st[t], q = st[HH + t];
    float mu = s * (1.f / NN);
    float var = q * (1.f / NN) - mu * mu;
    st[256 + t] = mu;
    st[384 + t] = rsqrtf(var + BN_EPS);
}

// h = relu(bn2(z2)) ; stats from d_statsB
__global__ void k_bn_relu(const float* __restrict__ z,
                          const float* __restrict__ g2, const float* __restrict__ b2) {
    int t = blockIdx.x * blockDim.x + threadIdx.x;
    if (t >= NN * 32) return;
    int c = (t & 31) * 4;
    const float* mu = d_statsB + 256;
    const float* rs = d_statsB + 384;
    float4 v = ((const float4*)z)[t];
    v.x = fmaxf((v.x - mu[c + 0]) * rs[c + 0] * g2[c + 0] + b2[c + 0], 0.f);
    v.y = fmaxf((v.y - mu[c + 1]) * rs[c + 1] * g2[c + 1] + b2[c + 1], 0.f);
    v.z = fmaxf((v.z - mu[c + 2]) * rs[c + 2] * g2[c + 2] + b2[c + 2], 0.f);
    v.w = fmaxf((v.w - mu[c + 3]) * rs[c + 3] * g2[c + 3] + b2[c + 3], 0.f);
    ((float4*)d_h)[t] = v;
}

// per-graph pooled sum of d_h into d_pool[g][layer*128 + c]
__global__ void k_pool(int layer) {
    int g = blockIdx.x;
    int c = threadIdx.x;   // 128
    int s = d_start[g], e = d_start[g + 1];
    float a0 = 0.f, a1 = 0.f, a2 = 0.f, a3 = 0.f;
    int n = s;
    for (; n + 3 < e; n += 4) {
        a0 += d_h[(size_t)(n + 0) * HH + c];
        a1 += d_h[(size_t)(n + 1) * HH + c];
        a2 += d_h[(size_t)(n + 2) * HH + c];
        a3 += d_h[(size_t)(n + 3) * HH + c];
    }
    for (; n < e; ++n) a0 += d_h[(size_t)n * HH + c];
    d_pool[(size_t)g * (LL * HH) + layer * HH + c] = (a0 + a1) + (a2 + a3);
}

// out[g] = relu(pool[g] @ fc1 + b1) @ fc2 + b2
__global__ void k_head(const float* __restrict__ fc1w, const float* __restrict__ fc1b,
                       const float* __restrict__ fc2w, const float* __restrict__ fc2b,
                       float* __restrict__ out) {
    __shared__ float sp[LL * HH];
    __shared__ float t1[HH];
    int g = blockIdx.x, t = threadIdx.x;   // 128 threads
    for (int k = t; k < LL * HH; k += HH) sp[k] = d_pool[(size_t)g * (LL * HH) + k];
    __syncthreads();
    float acc = fc1b[t];
#pragma unroll 8
    for (int k = 0; k < LL * HH; k++) acc += sp[k] * fc1w[(size_t)k * HH + t];
    t1[t] = fmaxf(acc, 0.f);
    __syncthreads();
    if (t < CC) {
        float a = fc2b[t];
#pragma unroll 8
        for (int j = 0; j < HH; j++) a += t1[j] * fc2w[j * CC + t];
        out[g * CC + t] = a;
    }
}

extern "C" void kernel_launch(void* const* d_in, const int* in_sizes, int n_in,
                              void* d_out, int out_size) {
    const float* x     = (const float*)d_in[0];
    const int*   ei    = (const int*)d_in[1];
    const int*   batch = (const int*)d_in[2];
    const float* W1    = (const float*)d_in[3];
    const float* b1    = (const float*)d_in[4];
    const float* g1    = (const float*)d_in[5];
    const float* bt1   = (const float*)d_in[6];
    const float* W2    = (const float*)d_in[7];
    const float* b2    = (const float*)d_in[8];
    const float* g2    = (const float*)d_in[9];
    const float* bt2   = (const float*)d_in[10];
    const float* eps   = (const float*)d_in[11];
    const float* fc1w  = (const float*)d_in[12];
    const float* fc1b  = (const float*)d_in[13];
    const float* fc2w  = (const float*)d_in[14];
    const float* fc2b  = (const float*)d_in[15];
    float* out = (float*)d_out;

    const int* src = ei;
    const int* dst = ei + EE;

    float *hbuf, *zbuf, *ybuf, *stA, *stB;
    cudaGetSymbolAddress((void**)&hbuf, d_h);
    cudaGetSymbolAddress((void**)&zbuf, d_z);
    cudaGetSymbolAddress((void**)&ybuf, d_y);
    cudaGetSymbolAddress((void**)&stA, d_statsA);
    cudaGetSymbolAddress((void**)&stB, d_statsB);

    const int elem_blocks = (NN * 32 + 255) / 256;           // 6250
    const int gemm_blocks = (NN + BM - 1) / BM;              // 391
    const int agg_blocks  = (NN * 32 + 255) / 256;           // warp per node

    // ---- one-time per launch: graph bounds + CSR build ----
    k_bounds<<<(NN + 255) / 256, 256>>>(batch);
    k_zero_cnt<<<(NN + 255) / 256, 256>>>();
    k_hist<<<(EE + 255) / 256, 256>>>(dst);
    k_scan<<<1, SCAN_T>>>();
    k_fill<<<(EE + 255) / 256, 256>>>(src, dst);

    for (int i = 0; i < LL; i++) {
        const float* hin = (i == 0) ? x : hbuf;
        k_zero_stats<<<1, 256>>>();
        k_agg<<<agg_blocks, 256>>>(hin, eps, i);
        // y = z @ W1[i] + b1[i]; stats -> A
        k_gemm<false><<<gemm_blocks, 256>>>(zbuf, W1 + (size_t)i * HH * HH,
                                            b1 + i * HH, nullptr, nullptr,
                                            ybuf, stA);
        k_finalize<<<1, HH>>>(stA);
        // z2 = relu(bn1(y)) @ W2[i] + b2[i]; stats -> B
        k_gemm<true><<<gemm_blocks, 256>>>(ybuf, W2 + (size_t)i * HH * HH,
                                           b2 + i * HH, g1 + i * HH, bt1 + i * HH,
                                           zbuf, stB);
        k_finalize<<<1, HH>>>(stB);
        k_bn_relu<<<elem_blocks, 256>>>(zbuf, g2 + i * HH, bt2 + i * HH);
        k_pool<<<GG, HH>>>(i);
    }

    k_head<<<GG, HH>>>(fc1w, fc1b, fc2w, fc2b, out);
}

// round 5
// speedup vs baseline: 1.5622x; 1.0810x over previous
#include <cuda_runtime.h>
#include <cuda_bf16.h>
#include <cstdint>

#define NN 50000
#define EE 600000
#define HH 128
#define LL 4
#define GG 256
#define CC 10
#define BN_EPS 1e-5f

// -------- device scratch (no allocations allowed) --------
__device__ float d_h[NN * HH];      // pre-BN z2 of current layer
__device__ float d_z[NN * HH];      // agg output
__device__ float d_y[NN * HH];      // GEMM1 output
__device__ float d_pool[GG * LL * HH];
__device__ float d_statsA[4 * HH];  // [0:128) sum, [128:256) sumsq, [256:384) mu, [384:512) rsigma
__device__ float d_statsB[4 * HH];
__device__ int   d_start[GG + 1];
// CSR (dst-sorted adjacency)
__device__ int   d_cnt[NN];
__device__ int   d_cur[NN];
__device__ int   d_rowptr[NN + 1];
__device__ int   d_col[EE];
__device__ int   d_bsum[256];
__device__ int   d_boff[256];

#define SCAN_BLOCKS ((NN + 255) / 256)   // 196

// -------- graph boundaries from sorted batch --------
__global__ void k_bounds(const int* __restrict__ batch) {
    int n = blockIdx.x * blockDim.x + threadIdx.x;
    if (n >= NN) return;
    int g = batch[n];
    if (n == 0) {
        for (int gg = 0; gg <= g; ++gg) d_start[gg] = 0;
    } else {
        int gp = batch[n - 1];
        for (int gg = gp + 1; gg <= g; ++gg) d_start[gg] = n;
    }
    if (n == NN - 1) {
        for (int gg = g + 1; gg <= GG; ++gg) d_start[gg] = NN;
    }
}

// -------- zero counters + stats in one launch --------
__global__ void k_zero_all() {
    int n = blockIdx.x * blockDim.x + threadIdx.x;
    if (n < NN) { d_cnt[n] = 0; d_cur[n] = 0; }
    if (blockIdx.x == 0) {
        int t = threadIdx.x;   // 256
        d_statsA[t] = 0.f;
        d_statsB[t] = 0.f;
    }
}

__global__ void k_hist(const int* __restrict__ dst) {
    int e = blockIdx.x * blockDim.x + threadIdx.x;
    if (e < EE) atomicAdd(&d_cnt[dst[e]], 1);
}

// scan stage 1: per-block totals
__global__ void k_scan1() {
    __shared__ int sp[256];
    int t = threadIdx.x;
    int i = blockIdx.x * 256 + t;
    int v = (i < NN) ? d_cnt[i] : 0;
    sp[t] = v;
    __syncthreads();
    for (int off = 128; off > 0; off >>= 1) {
        if (t < off) sp[t] += sp[t + off];
        __syncthreads();
    }
    if (t == 0) d_bsum[blockIdx.x] = sp[0];
}

// scan stage 2: exclusive scan of block totals (1 block)
__global__ void k_scan2() {
    __shared__ int sp[256];
    int t = threadIdx.x;
    int v = (t < SCAN_BLOCKS) ? d_bsum[t] : 0;
    sp[t] = v;
    __syncthreads();
    for (int off = 1; off < 256; off <<= 1) {
        int u = 0;
        if (t >= off) u = sp[t - off];
        __syncthreads();
        if (t >= off) sp[t] += u;
        __syncthreads();
    }
    d_boff[t] = sp[t] - v;   // exclusive
    if (t == 0) d_rowptr[NN] = EE;
}

// scan stage 3: per-block exclusive prefix + offset
__global__ void k_scan3() {
    __shared__ int sp[256];
    int t = threadIdx.x;
    int i = blockIdx.x * 256 + t;
    int v = (i < NN) ? d_cnt[i] : 0;
    sp[t] = v;
    __syncthreads();
    for (int off = 1; off < 256; off <<= 1) {
        int u = 0;
        if (t >= off) u = sp[t - off];
        __syncthreads();
        if (t >= off) sp[t] += u;
        __syncthreads();
    }
    if (i < NN) d_rowptr[i] = d_boff[blockIdx.x] + sp[t] - v;
}

__global__ void k_fill(const int* __restrict__ src, const int* __restrict__ dst) {
    int e = blockIdx.x * blockDim.x + threadIdx.x;
    if (e >= EE) return;
    int d = dst[e];
    int pos = atomicAdd(&d_cur[d], 1);
    d_col[d_rowptr[d] + pos] = src[e];
}

// -------- gather aggregation with lazy BN on input --------
// z[n] = (1+eps)*f(h[n]) + sum_{s in adj(n)} f(h[s]),  f = relu(bn2) (NORM) or identity
// one warp per node, lane owns one float4 column slice; 4-deep pipelined gather.
template <bool NORM>
__global__ __launch_bounds__(256) void k_agg(const float* __restrict__ hin,
                                             const float* __restrict__ eps, int layer,
                                             const float* __restrict__ g2,
                                             const float* __restrict__ bt2) {
    int t = blockIdx.x * blockDim.x + threadIdx.x;
    int n = t >> 5;
    int l = t & 31;
    if (n >= NN) return;

    float sc0 = 1.f, sc1 = 1.f, sc2 = 1.f, sc3 = 1.f;
    float sh0 = 0.f, sh1 = 0.f, sh2 = 0.f, sh3 = 0.f;
    if (NORM) {
        int c = l * 4;
        const float* mu = d_statsB + 256;
        const float* rs = d_statsB + 384;
        sc0 = rs[c + 0] * g2[c + 0]; sh0 = bt2[c + 0] - mu[c + 0] * sc0;
        sc1 = rs[c + 1] * g2[c + 1]; sh1 = bt2[c + 1] - mu[c + 1] * sc1;
        sc2 = rs[c + 2] * g2[c + 2]; sh2 = bt2[c + 2] - mu[c + 2] * sc2;
        sc3 = rs[c + 3] * g2[c + 3]; sh3 = bt2[c + 3] - mu[c + 3] * sc3;
    }

    const float4* h4 = (const float4*)hin;
    auto rd = [&](int node) -> float4 {
        float4 u = __ldg(&h4[(size_t)node * 32 + l]);
        if (NORM) {
            u.x = fmaxf(fmaf(u.x, sc0, sh0), 0.f);
            u.y = fmaxf(fmaf(u.y, sc1, sh1), 0.f);
            u.z = fmaxf(fmaf(u.z, sc2, sh2), 0.f);
            u.w = fmaxf(fmaf(u.w, sc3, sh3), 0.f);
        }
        return u;
    };

    float s = 1.f + __ldg(&eps[layer]);
    float4 v = rd(n);
    float ax = v.x * s, ay = v.y * s, az = v.z * s, aw = v.w * s;

    int p0 = d_rowptr[n], p1 = d_rowptr[n + 1];
    int p = p0;
    for (; p + 4 <= p1; p += 4) {
        int s0 = d_col[p + 0], s1 = d_col[p + 1], s2 = d_col[p + 2], s3 = d_col[p + 3];
        float4 u0 = rd(s0);
        float4 u1 = rd(s1);
        float4 u2 = rd(s2);
        float4 u3 = rd(s3);
        ax += (u0.x + u1.x) + (u2.x + u3.x);
        ay += (u0.y + u1.y) + (u2.y + u3.y);
        az += (u0.z + u1.z) + (u2.z + u3.z);
        aw += (u0.w + u1.w) + (u2.w + u3.w);
    }
    for (; p < p1; ++p) {
        float4 u = rd(d_col[p]);
        ax += u.x; ay += u.y; az += u.z; aw += u.w;
    }
    ((float4*)d_z)[(size_t)n * 32 + l] = make_float4(ax, ay, az, aw);
}

// -------- tiled SGEMM: out[N,128] = f(A)[N,128] @ W[128,128] + bias --------
#define BM 128
#define BK 8
template <bool BN_IN>
__global__ __launch_bounds__(256, 2) void k_gemm(
    const float* __restrict__ A, const float* __restrict__ W,
    const float* __restrict__ bias,
    const float* __restrict__ bng, const float* __restrict__ bnb,
    float* __restrict__ out, float* __restrict__ outstats) {

    __shared__ float As[2][BK][BM];
    __shared__ float Bs[2][BK][HH];
    __shared__ float s_sum[HH];
    __shared__ float s_sq[HH];

    int tid = threadIdx.x;
    int tx = tid & 15;     // col group (8 cols)
    int ty = tid >> 4;     // row group (8 rows)
    int row0 = blockIdx.x * BM;

    if (tid < HH) { s_sum[tid] = 0.f; s_sq[tid] = 0.f; }

    int a_row = tid >> 1;          // 0..127
    int a_k   = (tid & 1) * 4;     // 0 or 4
    int b_r   = tid >> 5;          // 0..7
    int b_c   = (tid & 31) * 4;    // 0..124

    const float* mu = d_statsA + 256;
    const float* rs = d_statsA + 384;

    float acc[8][8];
#pragma unroll
    for (int i = 0; i < 8; i++)
#pragma unroll
        for (int j = 0; j < 8; j++) acc[i][j] = 0.f;

    auto loadA = [&](int kt) -> float4 {
        int gr = row0 + a_row;
        float4 av = make_float4(0.f, 0.f, 0.f, 0.f);
        if (gr < NN) av = *(const float4*)(A + (size_t)gr * HH + kt + a_k);
        if (BN_IN) {
            int kg = kt + a_k;
            av.x = fmaxf((av.x - mu[kg + 0]) * rs[kg + 0] * bng[kg + 0] + bnb[kg + 0], 0.f);
            av.y = fmaxf((av.y - mu[kg + 1]) * rs[kg + 1] * bng[kg + 1] + bnb[kg + 1], 0.f);
            av.z = fmaxf((av.z - mu[kg + 2]) * rs[kg + 2] * bng[kg + 2] + bnb[kg + 2], 0.f);
            av.w = fmaxf((av.w - mu[kg + 3]) * rs[kg + 3] * bng[kg + 3] + bnb[kg + 3], 0.f);
        }
        return av;
    };

    {
        float4 av = loadA(0);
        float4 bv = *(const float4*)(W + (size_t)b_r * HH + b_c);
        As[0][a_k + 0][a_row] = av.x;
        As[0][a_k + 1][a_row] = av.y;
        As[0][a_k + 2][a_row] = av.z;
        As[0][a_k + 3][a_row] = av.w;
        *(float4*)&Bs[0][b_r][b_c] = bv;
    }
    __syncthreads();

    const int NIT = HH / BK;   // 16
    for (int it = 0; it < NIT; ++it) {
        int cur = it & 1, nxt = cur ^ 1;
        float4 av, bv;
        if (it + 1 < NIT) {
            int kt = (it + 1) * BK;
            av = loadA(kt);
            bv = *(const float4*)(W + (size_t)(kt + b_r) * HH + b_c);
        }

#pragma unroll
        for (int k = 0; k < BK; k++) {
            float ar[8], br[8];
            *(float4*)&ar[0] = *(const float4*)&As[cur][k][ty * 8];
            *(float4*)&ar[4] = *(const float4*)&As[cur][k][ty * 8 + 4];
            *(float4*)&br[0] = *(const float4*)&Bs[cur][k][tx * 8];
            *(float4*)&br[4] = *(const float4*)&Bs[cur][k][tx * 8 + 4];
#pragma unroll
            for (int i = 0; i < 8; i++)
#pragma unroll
                for (int j = 0; j < 8; j++) acc[i][j] += ar[i] * br[j];
        }

        if (it + 1 < NIT) {
            As[nxt][a_k + 0][a_row] = av.x;
            As[nxt][a_k + 1][a_row] = av.y;
            As[nxt][a_k + 2][a_row] = av.z;
            As[nxt][a_k + 3][a_row] = av.w;
            *(float4*)&Bs[nxt][b_r][b_c] = bv;
        }
        __syncthreads();
    }

    // epilogue: bias + store + channel stats
#pragma unroll
    for (int j = 0; j < 8; j++) {
        int c = tx * 8 + j;
        float bcol = bias[c];
        float psum = 0.f, psq = 0.f;
#pragma unroll
        for (int i = 0; i < 8; i++) {
            int gr = row0 + ty * 8 + i;
            if (gr < NN) {
                float v = acc[i][j] + bcol;
                out[(size_t)gr * HH + c] = v;
                psum += v;
                psq  += v * v;
            }
        }
        atomicAdd(&s_sum[c], psum);
        atomicAdd(&s_sq[c], psq);
    }
    __syncthreads();
    if (tid < HH) {
        atomicAdd(&outstats[tid], s_sum[tid]);
        atomicAdd(&outstats[HH + tid], s_sq[tid]);
    }
}

// finalize stats and zero accumulators for next use
__global__ void k_finalize(float* st) {
    int t = threadIdx.x;   // 128
    float s = st[t], q = st[HH + t];
    float mu = s * (1.f / NN);
    float var = q * (1.f / NN) - mu * mu;
    st[256 + t] = mu;
    st[384 + t] = rsqrtf(var + BN_EPS);
    st[t] = 0.f;
    st[HH + t] = 0.f;
}

// per-graph pooled sum of relu(bn2(d_h)) into d_pool[g][layer*128 + c]
__global__ void k_pool(int layer, const float* __restrict__ g2, const float* __restrict__ bt2) {
    int g = blockIdx.x;
    int c = threadIdx.x;   // 128
    const float* mu = d_statsB + 256;
    const float* rs = d_statsB + 384;
    float sc = rs[c] * g2[c];
    float sh = bt2[c] - mu[c] * sc;
    int s = d_start[g], e = d_start[g + 1];
    float a0 = 0.f, a1 = 0.f, a2 = 0.f, a3 = 0.f;
    float a4 = 0.f, a5 = 0.f, a6 = 0.f, a7 = 0.f;
    int n = s;
    for (; n + 8 <= e; n += 8) {
        a0 += fmaxf(fmaf(d_h[(size_t)(n + 0) * HH + c], sc, sh), 0.f);
        a1 += fmaxf(fmaf(d_h[(size_t)(n + 1) * HH + c], sc, sh), 0.f);
        a2 += fmaxf(fmaf(d_h[(size_t)(n + 2) * HH + c], sc, sh), 0.f);
        a3 += fmaxf(fmaf(d_h[(size_t)(n + 3) * HH + c], sc, sh), 0.f);
        a4 += fmaxf(fmaf(d_h[(size_t)(n + 4) * HH + c], sc, sh), 0.f);
        a5 += fmaxf(fmaf(d_h[(size_t)(n + 5) * HH + c], sc, sh), 0.f);
        a6 += fmaxf(fmaf(d_h[(size_t)(n + 6) * HH + c], sc, sh), 0.f);
        a7 += fmaxf(fmaf(d_h[(size_t)(n + 7) * HH + c], sc, sh), 0.f);
    }
    for (; n < e; ++n) a0 += fmaxf(fmaf(d_h[(size_t)n * HH + c], sc, sh), 0.f);
    d_pool[(size_t)g * (LL * HH) + layer * HH + c] =
        ((a0 + a1) + (a2 + a3)) + ((a4 + a5) + (a6 + a7));
}

// out[g] = relu(pool[g] @ fc1 + b1) @ fc2 + b2
__global__ void k_head(const float* __restrict__ fc1w, const float* __restrict__ fc1b,
                       const float* __restrict__ fc2w, const float* __restrict__ fc2b,
                       float* __restrict__ out) {
    __shared__ float sp[LL * HH];
    __shared__ float t1[HH];
    int g = blockIdx.x, t = threadIdx.x;   // 128 threads
    for (int k = t; k < LL * HH; k += HH) sp[k] = d_pool[(size_t)g * (LL * HH) + k];
    __syncthreads();
    float acc = fc1b[t];
#pragma unroll 8
    for (int k = 0; k < LL * HH; k++) acc += sp[k] * fc1w[(size_t)k * HH + t];
    t1[t] = fmaxf(acc, 0.f);
    __syncthreads();
    if (t < CC) {
        float a = fc2b[t];
#pragma unroll 8
        for (int j = 0; j < HH; j++) a += t1[j] * fc2w[j * CC + t];
        out[g * CC + t] = a;
    }
}

extern "C" void kernel_launch(void* const* d_in, const int* in_sizes, int n_in,
                              void* d_out, int out_size) {
    const float* x     = (const float*)d_in[0];
    const int*   ei    = (const int*)d_in[1];
    const int*   batch = (const int*)d_in[2];
    const float* W1    = (const float*)d_in[3];
    const float* b1    = (const float*)d_in[4];
    const float* g1    = (const float*)d_in[5];
    const float* bt1   = (const float*)d_in[6];
    const float* W2    = (const float*)d_in[7];
    const float* b2    = (const float*)d_in[8];
    const float* g2    = (const float*)d_in[9];
    const float* bt2   = (const float*)d_in[10];
    const float* eps   = (const float*)d_in[11];
    const float* fc1w  = (const float*)d_in[12];
    const float* fc1b  = (const float*)d_in[13];
    const float* fc2w  = (const float*)d_in[14];
    const float* fc2b  = (const float*)d_in[15];
    float* out = (float*)d_out;

    const int* src = ei;
    const int* dst = ei + EE;

    float *hbuf, *zbuf, *ybuf, *stA, *stB;
    cudaGetSymbolAddress((void**)&hbuf, d_h);
    cudaGetSymbolAddress((void**)&zbuf, d_z);
    cudaGetSymbolAddress((void**)&ybuf, d_y);
    cudaGetSymbolAddress((void**)&stA, d_statsA);
    cudaGetSymbolAddress((void**)&stB, d_statsB);

    const int gemm_blocks = (NN + BM - 1) / BM;              // 391
    const int agg_blocks  = (NN * 32 + 255) / 256;           // warp per node

    // ---- per-replay: graph bounds + CSR build ----
    k_bounds<<<SCAN_BLOCKS, 256>>>(batch);
    k_zero_all<<<SCAN_BLOCKS, 256>>>();
    k_hist<<<(EE + 255) / 256, 256>>>(dst);
    k_scan1<<<SCAN_BLOCKS, 256>>>();
    k_scan2<<<1, 256>>>();
    k_scan3<<<SCAN_BLOCKS, 256>>>();
    k_fill<<<(EE + 255) / 256, 256>>>(src, dst);

    for (int i = 0; i < LL; i++) {
        if (i == 0) {
            k_agg<false><<<agg_blocks, 256>>>(x, eps, i, nullptr, nullptr);
        } else {
            // lazy BN: normalize prev layer's pre-BN z2 (in d_h) with statsB + layer i-1 params
            k_agg<true><<<agg_blocks, 256>>>(hbuf, eps, i,
                                             g2 + (i - 1) * HH, bt2 + (i - 1) * HH);
        }
        // y = z @ W1[i] + b1[i]; stats -> A
        k_gemm<false><<<gemm_blocks, 256>>>(zbuf, W1 + (size_t)i * HH * HH,
                                            b1 + i * HH, nullptr, nullptr,
                                            ybuf, stA);
        k_finalize<<<1, HH>>>(stA);
        // z2 = relu(bn1(y)) @ W2[i] + b2[i]; stats -> B   (z2 stays pre-BN in d_h)
        k_gemm<true><<<gemm_blocks, 256>>>(ybuf, W2 + (size_t)i * HH * HH,
                                           b2 + i * HH, g1 + i * HH, bt1 + i * HH,
                                           hbuf, stB);
        k_finalize<<<1, HH>>>(stB);
        k_pool<<<GG, HH>>>(i, g2 + i * HH, bt2 + i * HH);
    }

    k_head<<<GG, HH>>>(fc1w, fc1b, fc2w, fc2b, out);
}

// round 6
// speedup vs baseline: 3.4373x; 2.2002x over previous
#include <cuda_runtime.h>
#include <cuda_bf16.h>
#include <cstdint>

#define NN 50000
#define EE 600000
#define HH 128
#define LL 4
#define GG 256
#define CC 10
#define BN_EPS 1e-5f

// -------- device scratch (no allocations allowed) --------
__device__ float d_h[NN * HH];      // pre-BN z2 of current layer
__device__ float d_z[NN * HH];      // agg output
__device__ float d_y[NN * HH];      // GEMM1 output
__device__ float d_pool[GG * LL * HH];
__device__ float d_statsA[4 * HH];  // [0:128) sum, [128:256) sumsq, [256:384) mu, [384:512) rsigma
__device__ float d_statsB[4 * HH];
__device__ int   d_start[GG + 1];
// CSR (dst-sorted adjacency)
__device__ int   d_cnt[NN];
__device__ int   d_cur[NN];
__device__ int   d_rowptr[NN + 1];
__device__ int   d_col[EE];
__device__ int   d_bsum[256];
__device__ int   d_boff[256];

#define SCAN_BLOCKS ((NN + 255) / 256)   // 196

// -------- graph boundaries from sorted batch --------
__global__ void k_bounds(const int* __restrict__ batch) {
    int n = blockIdx.x * blockDim.x + threadIdx.x;
    if (n >= NN) return;
    int g = batch[n];
    if (n == 0) {
        for (int gg = 0; gg <= g; ++gg) d_start[gg] = 0;
    } else {
        int gp = batch[n - 1];
        for (int gg = gp + 1; gg <= g; ++gg) d_start[gg] = n;
    }
    if (n == NN - 1) {
        for (int gg = g + 1; gg <= GG; ++gg) d_start[gg] = NN;
    }
}

// -------- zero counters + stats in one launch --------
__global__ void k_zero_all() {
    int n = blockIdx.x * blockDim.x + threadIdx.x;
    if (n < NN) { d_cnt[n] = 0; d_cur[n] = 0; }
    if (blockIdx.x == 0) {
        int t = threadIdx.x;   // 256
        d_statsA[t] = 0.f;
        d_statsB[t] = 0.f;
    }
}

__global__ void k_hist(const int* __restrict__ dst) {
    int e = blockIdx.x * blockDim.x + threadIdx.x;
    if (e < EE) atomicAdd(&d_cnt[dst[e]], 1);
}

// scan stage 1: per-block totals
__global__ void k_scan1() {
    __shared__ int sp[256];
    int t = threadIdx.x;
    int i = blockIdx.x * 256 + t;
    int v = (i < NN) ? d_cnt[i] : 0;
    sp[t] = v;
    __syncthreads();
    for (int off = 128; off > 0; off >>= 1) {
        if (t < off) sp[t] += sp[t + off];
        __syncthreads();
    }
    if (t == 0) d_bsum[blockIdx.x] = sp[0];
}

// scan stage 2: exclusive scan of block totals (1 block)
__global__ void k_scan2() {
    __shared__ int sp[256];
    int t = threadIdx.x;
    int v = (t < SCAN_BLOCKS) ? d_bsum[t] : 0;
    sp[t] = v;
    __syncthreads();
    for (int off = 1; off < 256; off <<= 1) {
        int u = 0;
        if (t >= off) u = sp[t - off];
        __syncthreads();
        if (t >= off) sp[t] += u;
        __syncthreads();
    }
    d_boff[t] = sp[t] - v;   // exclusive
    if (t == 0) d_rowptr[NN] = EE;
}

// scan stage 3: per-block exclusive prefix + offset
__global__ void k_scan3() {
    __shared__ int sp[256];
    int t = threadIdx.x;
    int i = blockIdx.x * 256 + t;
    int v = (i < NN) ? d_cnt[i] : 0;
    sp[t] = v;
    __syncthreads();
    for (int off = 1; off < 256; off <<= 1) {
        int u = 0;
        if (t >= off) u = sp[t - off];
        __syncthreads();
        if (t >= off) sp[t] += u;
        __syncthreads();
    }
    if (i < NN) d_rowptr[i] = d_boff[blockIdx.x] + sp[t] - v;
}

__global__ void k_fill(const int* __restrict__ src, const int* __restrict__ dst) {
    int e = blockIdx.x * blockDim.x + threadIdx.x;
    if (e >= EE) return;
    int d = dst[e];
    int pos = atomicAdd(&d_cur[d], 1);
    d_col[d_rowptr[d] + pos] = src[e];
}

// -------- gather aggregation with lazy BN on input --------
template <bool NORM>
__global__ __launch_bounds__(256) void k_agg(const float* __restrict__ hin,
                                             const float* __restrict__ eps, int layer,
                                             const float* __restrict__ g2,
                                             const float* __restrict__ bt2) {
    int t = blockIdx.x * blockDim.x + threadIdx.x;
    int n = t >> 5;
    int l = t & 31;
    if (n >= NN) return;

    float sc0 = 1.f, sc1 = 1.f, sc2 = 1.f, sc3 = 1.f;
    float sh0 = 0.f, sh1 = 0.f, sh2 = 0.f, sh3 = 0.f;
    if (NORM) {
        int c = l * 4;
        const float* mu = d_statsB + 256;
        const float* rs = d_statsB + 384;
        sc0 = rs[c + 0] * g2[c + 0]; sh0 = bt2[c + 0] - mu[c + 0] * sc0;
        sc1 = rs[c + 1] * g2[c + 1]; sh1 = bt2[c + 1] - mu[c + 1] * sc1;
        sc2 = rs[c + 2] * g2[c + 2]; sh2 = bt2[c + 2] - mu[c + 2] * sc2;
        sc3 = rs[c + 3] * g2[c + 3]; sh3 = bt2[c + 3] - mu[c + 3] * sc3;
    }

    const float4* h4 = (const float4*)hin;
    auto rd = [&](int node) -> float4 {
        float4 u = __ldg(&h4[(size_t)node * 32 + l]);
        if (NORM) {
            u.x = fmaxf(fmaf(u.x, sc0, sh0), 0.f);
            u.y = fmaxf(fmaf(u.y, sc1, sh1), 0.f);
            u.z = fmaxf(fmaf(u.z, sc2, sh2), 0.f);
            u.w = fmaxf(fmaf(u.w, sc3, sh3), 0.f);
        }
        return u;
    };

    float s = 1.f + __ldg(&eps[layer]);
    float4 v = rd(n);
    float ax = v.x * s, ay = v.y * s, az = v.z * s, aw = v.w * s;

    int p0 = d_rowptr[n], p1 = d_rowptr[n + 1];
    int p = p0;
    for (; p + 4 <= p1; p += 4) {
        int s0 = d_col[p + 0], s1 = d_col[p + 1], s2 = d_col[p + 2], s3 = d_col[p + 3];
        float4 u0 = rd(s0);
        float4 u1 = rd(s1);
        float4 u2 = rd(s2);
        float4 u3 = rd(s3);
        ax += (u0.x + u1.x) + (u2.x + u3.x);
        ay += (u0.y + u1.y) + (u2.y + u3.y);
        az += (u0.z + u1.z) + (u2.z + u3.z);
        aw += (u0.w + u1.w) + (u2.w + u3.w);
    }
    for (; p < p1; ++p) {
        float4 u = rd(d_col[p]);
        ax += u.x; ay += u.y; az += u.z; aw += u.w;
    }
    ((float4*)d_z)[(size_t)n * 32 + l] = make_float4(ax, ay, az, aw);
}

// -------- TF32 tensor-core GEMM: out[N,128] = f(A)[N,128] @ W[128,128] + bias --------
// smem layout (4-byte words):
//   Ws  : [0, 16896)        128 x 132 (tf32 bits)
//   As  : [16896, 26112)    2 x 128 x 36 (tf32 bits)
//   ssum: [26112, 26240)    float
//   ssq : [26240, 26368)    float
#define GEMM_SMEM_WORDS 26368
#define GEMM_SMEM_BYTES (GEMM_SMEM_WORDS * 4)

__device__ __forceinline__ uint32_t f2tf32(float f) {
    uint32_t o;
    asm("cvt.rna.tf32.f32 %0, %1;" : "=r"(o) : "f"(f));
    return o;
}

__device__ __forceinline__ void mma_tf32(float& c0, float& c1, float& c2, float& c3,
                                         uint32_t a0, uint32_t a1, uint32_t a2, uint32_t a3,
                                         uint32_t b0, uint32_t b1) {
    asm volatile(
        "mma.sync.aligned.m16n8k8.row.col.f32.tf32.tf32.f32 "
        "{%0,%1,%2,%3}, {%4,%5,%6,%7}, {%8,%9}, {%0,%1,%2,%3};"
        : "+f"(c0), "+f"(c1), "+f"(c2), "+f"(c3)
        : "r"(a0), "r"(a1), "r"(a2), "r"(a3), "r"(b0), "r"(b1));
}

template <bool BN_IN>
__global__ __launch_bounds__(256) void k_gemm_tc(
    const float* __restrict__ A, const float* __restrict__ W,
    const float* __restrict__ bias,
    const float* __restrict__ bng, const float* __restrict__ bnb,
    float* __restrict__ out, float* __restrict__ outstats) {

    extern __shared__ uint32_t sm[];
    uint32_t* Ws = sm;                     // [128][132]
    uint32_t* As = sm + 16896;             // [2][128][36]
    float* ssum = (float*)(sm + 26112);
    float* ssq  = (float*)(sm + 26240);

    int tid = threadIdx.x;
    int lane = tid & 31;
    int warp = tid >> 5;
    int m0 = (warp >> 1) * 32;             // warp row offset within tile
    int n0 = (warp & 1) * 64;              // warp col offset
    int row0 = blockIdx.x * 128;

    if (tid < HH) { ssum[tid] = 0.f; ssq[tid] = 0.f; }

    // stage W -> smem (tf32 rounded)
    const float4* W4 = (const float4*)W;
#pragma unroll
    for (int i = 0; i < 16; i++) {
        int f = tid + i * 256;             // 0..4095
        int k = f >> 5, c = f & 31;
        float4 w = W4[k * 32 + c];
        uint32_t* dst = Ws + k * 132 + c * 4;
        dst[0] = f2tf32(w.x); dst[1] = f2tf32(w.y);
        dst[2] = f2tf32(w.z); dst[3] = f2tf32(w.w);
    }

    const float* mu = d_statsA + 256;
    const float* rs = d_statsA + 384;
    const float4* A4 = (const float4*)A;

    auto loadA = [&](int kt, int buf) {
        uint32_t* dstb = As + buf * 4608;
#pragma unroll
        for (int i = 0; i < 4; i++) {
            int f = tid + i * 256;         // 0..1023
            int r = f >> 3, c8 = f & 7;
            int gcol = kt + c8 * 4;
            float4 v = make_float4(0.f, 0.f, 0.f, 0.f);
            int gr = row0 + r;
            if (gr < NN) v = A4[(size_t)gr * 32 + (kt >> 2) + c8];
            if (BN_IN) {
                v.x = fmaxf((v.x - mu[gcol + 0]) * rs[gcol + 0] * bng[gcol + 0] + bnb[gcol + 0], 0.f);
                v.y = fmaxf((v.y - mu[gcol + 1]) * rs[gcol + 1] * bng[gcol + 1] + bnb[gcol + 1], 0.f);
                v.z = fmaxf((v.z - mu[gcol + 2]) * rs[gcol + 2] * bng[gcol + 2] + bnb[gcol + 2], 0.f);
                v.w = fmaxf((v.w - mu[gcol + 3]) * rs[gcol + 3] * bng[gcol + 3] + bnb[gcol + 3], 0.f);
            }
            uint32_t* dst = dstb + r * 36 + c8 * 4;
            dst[0] = f2tf32(v.x); dst[1] = f2tf32(v.y);
            dst[2] = f2tf32(v.z); dst[3] = f2tf32(v.w);
        }
    };

    float acc[2][8][4];
#pragma unroll
    for (int mi = 0; mi < 2; mi++)
#pragma unroll
        for (int ni = 0; ni < 8; ni++)
#pragma unroll
            for (int r = 0; r < 4; r++) acc[mi][ni][r] = 0.f;

    loadA(0, 0);
    __syncthreads();

#pragma unroll
    for (int ch = 0; ch < 4; ch++) {
        if (ch < 3) loadA((ch + 1) * 32, (ch + 1) & 1);
        uint32_t* Ab = As + (ch & 1) * 4608;
        int ktg = ch * 32;
#pragma unroll
        for (int ks = 0; ks < 4; ks++) {
            int kl = ks * 8 + (lane & 3);
            uint32_t a[2][4];
#pragma unroll
            for (int mi = 0; mi < 2; mi++) {
                int r = m0 + mi * 16 + (lane >> 2);
                a[mi][0] = Ab[r * 36 + kl];
                a[mi][1] = Ab[(r + 8) * 36 + kl];
                a[mi][2] = Ab[r * 36 + kl + 4];
                a[mi][3] = Ab[(r + 8) * 36 + kl + 4];
            }
            int kg = ktg + ks * 8 + (lane & 3);
            uint32_t b[8][2];
#pragma unroll
            for (int ni = 0; ni < 8; ni++) {
                int nc = n0 + ni * 8 + (lane >> 2);
                b[ni][0] = Ws[kg * 132 + nc];
                b[ni][1] = Ws[(kg + 4) * 132 + nc];
            }
#pragma unroll
            for (int mi = 0; mi < 2; mi++)
#pragma unroll
                for (int ni = 0; ni < 8; ni++)
                    mma_tf32(acc[mi][ni][0], acc[mi][ni][1], acc[mi][ni][2], acc[mi][ni][3],
                             a[mi][0], a[mi][1], a[mi][2], a[mi][3],
                             b[ni][0], b[ni][1]);
        }
        __syncthreads();
    }

    // epilogue: bias + store + per-channel stats
    float psum[16], psq[16];
#pragma unroll
    for (int i = 0; i < 16; i++) { psum[i] = 0.f; psq[i] = 0.f; }

#pragma unroll
    for (int ni = 0; ni < 8; ni++) {
        int col = n0 + ni * 8 + 2 * (lane & 3);
        float b0v = bias[col], b1v = bias[col + 1];
#pragma unroll
        for (int mi = 0; mi < 2; mi++) {
            int r = row0 + m0 + mi * 16 + (lane >> 2);
            float v0 = acc[mi][ni][0] + b0v;
            float v1 = acc[mi][ni][1] + b1v;
            float v2 = acc[mi][ni][2] + b0v;
            float v3 = acc[mi][ni][3] + b1v;
            if (r < NN) {
                float2 st0 = make_float2(v0, v1);
                *(float2*)(out + (size_t)r * HH + col) = st0;
                psum[ni * 2]     += v0;  psq[ni * 2]     += v0 * v0;
                psum[ni * 2 + 1] += v1;  psq[ni * 2 + 1] += v1 * v1;
            }
            if (r + 8 < NN) {
                float2 st1 = make_float2(v2, v3);
                *(float2*)(out + (size_t)(r + 8) * HH + col) = st1;
                psum[ni * 2]     += v2;  psq[ni * 2]     += v2 * v2;
                psum[ni * 2 + 1] += v3;  psq[ni * 2 + 1] += v3 * v3;
            }
        }
    }

    // reduce across the 8 lanes sharing the same (lane & 3)
#pragma unroll
    for (int mask = 4; mask <= 16; mask <<= 1) {
#pragma unroll
        for (int i = 0; i < 16; i++) {
            psum[i] += __shfl_xor_sync(0xffffffff, psum[i], mask);
            psq[i]  += __shfl_xor_sync(0xffffffff, psq[i], mask);
        }
    }
    if (lane < 4) {
#pragma unroll
        for (int i = 0; i < 16; i++) {
            int col = n0 + 8 * (i >> 1) + 2 * lane + (i & 1);
            atomicAdd(&ssum[col], psum[i]);
            atomicAdd(&ssq[col], psq[i]);
        }
    }
    __syncthreads();
    if (tid < HH) {
        atomicAdd(&outstats[tid], ssum[tid]);
        atomicAdd(&outstats[HH + tid], ssq[tid]);
    }
}

// finalize stats and zero accumulators for next use
__global__ void k_finalize(float* st) {
    int t = threadIdx.x;   // 128
    float s = st[t], q = st[HH + t];
    float mu = s * (1.f / NN);
    float var = q * (1.f / NN) - mu * mu;
    st[256 + t] = mu;
    st[384 + t] = rsqrtf(var + BN_EPS);
    st[t] = 0.f;
    st[HH + t] = 0.f;
}

// per-graph pooled sum of relu(bn2(d_h)) into d_pool[g][layer*128 + c]
__global__ void k_pool(int layer, const float* __restrict__ g2, const float* __restrict__ bt2) {
    int g = blockIdx.x;
    int c = threadIdx.x;   // 128
    const float* mu = d_statsB + 256;
    const float* rs = d_statsB + 384;
    float sc = rs[c] * g2[c];
    float sh = bt2[c] - mu[c] * sc;
    int s = d_start[g], e = d_start[g + 1];
    float a0 = 0.f, a1 = 0.f, a2 = 0.f, a3 = 0.f;
    float a4 = 0.f, a5 = 0.f, a6 = 0.f, a7 = 0.f;
    int n = s;
    for (; n + 8 <= e; n += 8) {
        a0 += fmaxf(fmaf(d_h[(size_t)(n + 0) * HH + c], sc, sh), 0.f);
        a1 += fmaxf(fmaf(d_h[(size_t)(n + 1) * HH + c], sc, sh), 0.f);
        a2 += fmaxf(fmaf(d_h[(size_t)(n + 2) * HH + c], sc, sh), 0.f);
        a3 += fmaxf(fmaf(d_h[(size_t)(n + 3) * HH + c], sc, sh), 0.f);
        a4 += fmaxf(fmaf(d_h[(size_t)(n + 4) * HH + c], sc, sh), 0.f);
        a5 += fmaxf(fmaf(d_h[(size_t)(n + 5) * HH + c], sc, sh), 0.f);
        a6 += fmaxf(fmaf(d_h[(size_t)(n + 6) * HH + c], sc, sh), 0.f);
        a7 += fmaxf(fmaf(d_h[(size_t)(n + 7) * HH + c], sc, sh), 0.f);
    }
    for (; n < e; ++n) a0 += fmaxf(fmaf(d_h[(size_t)n * HH + c], sc, sh), 0.f);
    d_pool[(size_t)g * (LL * HH) + layer * HH + c] =
        ((a0 + a1) + (a2 + a3)) + ((a4 + a5) + (a6 + a7));
}

// out[g] = relu(pool[g] @ fc1 + b1) @ fc2 + b2
__global__ void k_head(const float* __restrict__ fc1w, const float* __restrict__ fc1b,
                       const float* __restrict__ fc2w, const float* __restrict__ fc2b,
                       float* __restrict__ out) {
    __shared__ float sp[LL * HH];
    __shared__ float t1[HH];
    int g = blockIdx.x, t = threadIdx.x;   // 128 threads
    for (int k = t; k < LL * HH; k += HH) sp[k] = d_pool[(size_t)g * (LL * HH) + k];
    __syncthreads();
    float acc = fc1b[t];
#pragma unroll 8
    for (int k = 0; k < LL * HH; k++) acc += sp[k] * fc1w[(size_t)k * HH + t];
    t1[t] = fmaxf(acc, 0.f);
    __syncthreads();
    if (t < CC) {
        float a = fc2b[t];
#pragma unroll 8
        for (int j = 0; j < HH; j++) a += t1[j] * fc2w[j * CC + t];
        out[g * CC + t] = a;
    }
}

extern "C" void kernel_launch(void* const* d_in, const int* in_sizes, int n_in,
                              void* d_out, int out_size) {
    const float* x     = (const float*)d_in[0];
    const int*   ei    = (const int*)d_in[1];
    const int*   batch = (const int*)d_in[2];
    const float* W1    = (const float*)d_in[3];
    const float* b1    = (const float*)d_in[4];
    const float* g1    = (const float*)d_in[5];
    const float* bt1   = (const float*)d_in[6];
    const float* W2    = (const float*)d_in[7];
    const float* b2    = (const float*)d_in[8];
    const float* g2    = (const float*)d_in[9];
    const float* bt2   = (const float*)d_in[10];
    const float* eps   = (const float*)d_in[11];
    const float* fc1w  = (const float*)d_in[12];
    const float* fc1b  = (const float*)d_in[13];
    const float* fc2w  = (const float*)d_in[14];
    const float* fc2b  = (const float*)d_in[15];
    float* out = (float*)d_out;

    const int* src = ei;
    const int* dst = ei + EE;

    float *hbuf, *zbuf, *ybuf, *stA, *stB;
    cudaGetSymbolAddress((void**)&hbuf, d_h);
    cudaGetSymbolAddress((void**)&zbuf, d_z);
    cudaGetSymbolAddress((void**)&ybuf, d_y);
    cudaGetSymbolAddress((void**)&stA, d_statsA);
    cudaGetSymbolAddress((void**)&stB, d_statsB);

    cudaFuncSetAttribute(k_gemm_tc<false>, cudaFuncAttributeMaxDynamicSharedMemorySize, GEMM_SMEM_BYTES);
    cudaFuncSetAttribute(k_gemm_tc<true>,  cudaFuncAttributeMaxDynamicSharedMemorySize, GEMM_SMEM_BYTES);

    const int gemm_blocks = (NN + 127) / 128;                // 391
    const int agg_blocks  = (NN * 32 + 255) / 256;           // warp per node

    // ---- per-replay: graph bounds + CSR build ----
    k_bounds<<<SCAN_BLOCKS, 256>>>(batch);
    k_zero_all<<<SCAN_BLOCKS, 256>>>();
    k_hist<<<(EE + 255) / 256, 256>>>(dst);
    k_scan1<<<SCAN_BLOCKS, 256>>>();
    k_scan2<<<1, 256>>>();
    k_scan3<<<SCAN_BLOCKS, 256>>>();
    k_fill<<<(EE + 255) / 256, 256>>>(src, dst);

    for (int i = 0; i < LL; i++) {
        if (i == 0) {
            k_agg<false><<<agg_blocks, 256>>>(x, eps, i, nullptr, nullptr);
        } else {
            k_agg<true><<<agg_blocks, 256>>>(hbuf, eps, i,
                                             g2 + (i - 1) * HH, bt2 + (i - 1) * HH);
        }
        // y = z @ W1[i] + b1[i]; stats -> A
        k_gemm_tc<false><<<gemm_blocks, 256, GEMM_SMEM_BYTES>>>(
            zbuf, W1 + (size_t)i * HH * HH, b1 + i * HH, nullptr, nullptr, ybuf, stA);
        k_finalize<<<1, HH>>>(stA);
        // z2 = relu(bn1(y)) @ W2[i] + b2[i]; stats -> B   (z2 stays pre-BN in d_h)
        k_gemm_tc<true><<<gemm_blocks, 256, GEMM_SMEM_BYTES>>>(
            ybuf, W2 + (size_t)i * HH * HH, b2 + i * HH, g1 + i * HH, bt1 + i * HH, hbuf, stB);
        k_finalize<<<1, HH>>>(stB);
        k_pool<<<GG, HH>>>(i, g2 + i * HH, bt2 + i * HH);
    }

    k_head<<<GG, HH>>>(fc1w, fc1b, fc2w, fc2b, out);
}

// round 7
// speedup vs baseline: 3.5000x; 1.0182x over previous
#include <cuda_runtime.h>
#include <cuda_bf16.h>
#include <cstdint>

#define NN 50000
#define EE 600000
#define HH 128
#define LL 4
#define GG 256
#define CC 10
#define BN_EPS 1e-5f

// -------- device scratch (no allocations allowed) --------
__device__ float d_h[NN * HH];      // pre-BN z2 of current layer
__device__ float d_z[NN * HH];      // agg output
__device__ float d_y[NN * HH];      // GEMM1 output
__device__ float d_pool[GG * LL * HH];
__device__ float d_stA[LL][2 * HH]; // raw per-layer stats: [0:128) sum, [128:256) sumsq
__device__ float d_stB[LL][2 * HH];
__device__ int   d_start[GG + 1];
// CSR (dst-sorted adjacency)
__device__ int   d_cnt[NN];
__device__ int   d_cur[NN];
__device__ int   d_rowptr[NN + 1];
__device__ int   d_col[EE];
__device__ int   d_bsum[256];
__device__ int   d_boff[256];

#define SCAN_BLOCKS ((NN + 255) / 256)   // 196

// -------- init: graph bounds + zero counters + zero stats (one kernel) --------
__global__ void k_init(const int* __restrict__ batch) {
    int n = blockIdx.x * blockDim.x + threadIdx.x;
    if (n < NN) {
        d_cnt[n] = 0;
        d_cur[n] = 0;
        int g = batch[n];
        if (n == 0) {
            for (int gg = 0; gg <= g; ++gg) d_start[gg] = 0;
        } else {
            int gp = batch[n - 1];
            for (int gg = gp + 1; gg <= g; ++gg) d_start[gg] = n;
        }
        if (n == NN - 1) {
            for (int gg = g + 1; gg <= GG; ++gg) d_start[gg] = NN;
        }
    }
    if (n < LL * 2 * HH) {
        ((float*)d_stA)[n] = 0.f;
        ((float*)d_stB)[n] = 0.f;
    }
}

// -------- CSR build (4 edges/thread) --------
__global__ void k_hist(const int* __restrict__ dst) {
    int i = blockIdx.x * blockDim.x + threadIdx.x;
    if (i >= EE / 4) return;
    int4 d = ((const int4*)dst)[i];
    atomicAdd(&d_cnt[d.x], 1);
    atomicAdd(&d_cnt[d.y], 1);
    atomicAdd(&d_cnt[d.z], 1);
    atomicAdd(&d_cnt[d.w], 1);
}

// scan stage 1: per-block totals
__global__ void k_scan1() {
    __shared__ int sp[256];
    int t = threadIdx.x;
    int i = blockIdx.x * 256 + t;
    int v = (i < NN) ? d_cnt[i] : 0;
    sp[t] = v;
    __syncthreads();
    for (int off = 128; off > 0; off >>= 1) {
        if (t < off) sp[t] += sp[t + off];
        __syncthreads();
    }
    if (t == 0) d_bsum[blockIdx.x] = sp[0];
}

// scan stage 2: exclusive scan of block totals (1 block)
__global__ void k_scan2() {
    __shared__ int sp[256];
    int t = threadIdx.x;
    int v = (t < SCAN_BLOCKS) ? d_bsum[t] : 0;
    sp[t] = v;
    __syncthreads();
    for (int off = 1; off < 256; off <<= 1) {
        int u = 0;
        if (t >= off) u = sp[t - off];
        __syncthreads();
        if (t >= off) sp[t] += u;
        __syncthreads();
    }
    d_boff[t] = sp[t] - v;   // exclusive
    if (t == 0) d_rowptr[NN] = EE;
}

// scan stage 3: per-block exclusive prefix + offset
__global__ void k_scan3() {
    __shared__ int sp[256];
    int t = threadIdx.x;
    int i = blockIdx.x * 256 + t;
    int v = (i < NN) ? d_cnt[i] : 0;
    sp[t] = v;
    __syncthreads();
    for (int off = 1; off < 256; off <<= 1) {
        int u = 0;
        if (t >= off) u = sp[t - off];
        __syncthreads();
        if (t >= off) sp[t] += u;
        __syncthreads();
    }
    if (i < NN) d_rowptr[i] = d_boff[blockIdx.x] + sp[t] - v;
}

__global__ void k_fill(const int* __restrict__ src, const int* __restrict__ dst) {
    int i = blockIdx.x * blockDim.x + threadIdx.x;
    if (i >= EE / 4) return;
    int4 d = ((const int4*)dst)[i];
    int4 s = ((const int4*)src)[i];
    int p;
    p = atomicAdd(&d_cur[d.x], 1); d_col[d_rowptr[d.x] + p] = s.x;
    p = atomicAdd(&d_cur[d.y], 1); d_col[d_rowptr[d.y] + p] = s.y;
    p = atomicAdd(&d_cur[d.z], 1); d_col[d_rowptr[d.z] + p] = s.z;
    p = atomicAdd(&d_cur[d.w], 1); d_col[d_rowptr[d.w] + p] = s.w;
}

// -------- gather aggregation with lazy BN on input --------
// z[n] = (1+eps)*f(h[n]) + sum_{s in adj(n)} f(h[s]),  f = relu(bn2) (NORM) or identity
// statsPrev = raw sums of previous layer's statsB (NORM only)
template <bool NORM>
__global__ __launch_bounds__(256) void k_agg(const float* __restrict__ hin,
                                             const float* __restrict__ eps, int layer,
                                             const float* __restrict__ g2,
                                             const float* __restrict__ bt2,
                                             const float* __restrict__ statsPrev) {
    int t = blockIdx.x * blockDim.x + threadIdx.x;
    int n = t >> 5;
    int l = t & 31;
    if (n >= NN) return;

    float sc0 = 1.f, sc1 = 1.f, sc2 = 1.f, sc3 = 1.f;
    float sh0 = 0.f, sh1 = 0.f, sh2 = 0.f, sh3 = 0.f;
    if (NORM) {
        int c = l * 4;
#pragma unroll
        for (int j = 0; j < 4; j++) {
            float s = __ldg(&statsPrev[c + j]);
            float q = __ldg(&statsPrev[HH + c + j]);
            float m = s * (1.f / NN);
            float var = q * (1.f / NN) - m * m;
            float rs_ = rsqrtf(var + BN_EPS);
            float sc = rs_ * __ldg(&g2[c + j]);
            float sh = __ldg(&bt2[c + j]) - m * sc;
            if (j == 0) { sc0 = sc; sh0 = sh; }
            else if (j == 1) { sc1 = sc; sh1 = sh; }
            else if (j == 2) { sc2 = sc; sh2 = sh; }
            else { sc3 = sc; sh3 = sh; }
        }
    }

    const float4* h4 = (const float4*)hin;
    auto rd = [&](int node) -> float4 {
        float4 u = __ldg(&h4[(size_t)node * 32 + l]);
        if (NORM) {
            u.x = fmaxf(fmaf(u.x, sc0, sh0), 0.f);
            u.y = fmaxf(fmaf(u.y, sc1, sh1), 0.f);
            u.z = fmaxf(fmaf(u.z, sc2, sh2), 0.f);
            u.w = fmaxf(fmaf(u.w, sc3, sh3), 0.f);
        }
        return u;
    };

    float s = 1.f + __ldg(&eps[layer]);
    float4 v = rd(n);
    float ax = v.x * s, ay = v.y * s, az = v.z * s, aw = v.w * s;

    int p0 = d_rowptr[n], p1 = d_rowptr[n + 1];
    int p = p0;
    for (; p + 8 <= p1; p += 8) {
        int i0 = d_col[p + 0], i1 = d_col[p + 1], i2 = d_col[p + 2], i3 = d_col[p + 3];
        int i4 = d_col[p + 4], i5 = d_col[p + 5], i6 = d_col[p + 6], i7 = d_col[p + 7];
        float4 u0 = rd(i0), u1 = rd(i1), u2 = rd(i2), u3 = rd(i3);
        float4 u4 = rd(i4), u5 = rd(i5), u6 = rd(i6), u7 = rd(i7);
        ax += ((u0.x + u1.x) + (u2.x + u3.x)) + ((u4.x + u5.x) + (u6.x + u7.x));
        ay += ((u0.y + u1.y) + (u2.y + u3.y)) + ((u4.y + u5.y) + (u6.y + u7.y));
        az += ((u0.z + u1.z) + (u2.z + u3.z)) + ((u4.z + u5.z) + (u6.z + u7.z));
        aw += ((u0.w + u1.w) + (u2.w + u3.w)) + ((u4.w + u5.w) + (u6.w + u7.w));
    }
    for (; p + 4 <= p1; p += 4) {
        int i0 = d_col[p + 0], i1 = d_col[p + 1], i2 = d_col[p + 2], i3 = d_col[p + 3];
        float4 u0 = rd(i0), u1 = rd(i1), u2 = rd(i2), u3 = rd(i3);
        ax += (u0.x + u1.x) + (u2.x + u3.x);
        ay += (u0.y + u1.y) + (u2.y + u3.y);
        az += (u0.z + u1.z) + (u2.z + u3.z);
        aw += (u0.w + u1.w) + (u2.w + u3.w);
    }
    for (; p < p1; ++p) {
        float4 u = rd(d_col[p]);
        ax += u.x; ay += u.y; az += u.z; aw += u.w;
    }
    ((float4*)d_z)[(size_t)n * 32 + l] = make_float4(ax, ay, az, aw);
}

// -------- TF32 tensor-core GEMM: out[N,128] = f(A)[N,128] @ W[128,128] + bias --------
// smem layout (4-byte words):
//   Ws  : [0, 16896)        128 x 132 (tf32 bits)
//   As  : [16896, 26112)    2 x 128 x 36 (tf32 bits)
//   ssum: [26112, 26240)    float
//   ssq : [26240, 26368)    float
//   smu : [26368, 26496)    float (BN_IN only)
//   srs : [26496, 26624)    float (BN_IN only)
#define GEMM_SMEM_WORDS 26624
#define GEMM_SMEM_BYTES (GEMM_SMEM_WORDS * 4)

__device__ __forceinline__ uint32_t f2tf32(float f) {
    uint32_t o;
    asm("cvt.rna.tf32.f32 %0, %1;" : "=r"(o) : "f"(f));
    return o;
}

__device__ __forceinline__ void mma_tf32(float& c0, float& c1, float& c2, float& c3,
                                         uint32_t a0, uint32_t a1, uint32_t a2, uint32_t a3,
                                         uint32_t b0, uint32_t b1) {
    asm volatile(
        "mma.sync.aligned.m16n8k8.row.col.f32.tf32.tf32.f32 "
        "{%0,%1,%2,%3}, {%4,%5,%6,%7}, {%8,%9}, {%0,%1,%2,%3};"
        : "+f"(c0), "+f"(c1), "+f"(c2), "+f"(c3)
        : "r"(a0), "r"(a1), "r"(a2), "r"(a3), "r"(b0), "r"(b1));
}

template <bool BN_IN>
__global__ __launch_bounds__(256) void k_gemm_tc(
    const float* __restrict__ A, const float* __restrict__ W,
    const float* __restrict__ bias,
    const float* __restrict__ bng, const float* __restrict__ bnb,
    const float* __restrict__ instats,   // raw sums (BN_IN only)
    float* __restrict__ out, float* __restrict__ outstats) {

    extern __shared__ uint32_t sm[];
    uint32_t* Ws = sm;                     // [128][132]
    uint32_t* As = sm + 16896;             // [2][128][36]
    float* ssum = (float*)(sm + 26112);
    float* ssq  = (float*)(sm + 26240);
    float* smu  = (float*)(sm + 26368);
    float* srs  = (float*)(sm + 26496);

    int tid = threadIdx.x;
    int lane = tid & 31;
    int warp = tid >> 5;
    int m0 = (warp >> 1) * 32;             // warp row offset within tile
    int n0 = (warp & 1) * 64;              // warp col offset
    int row0 = blockIdx.x * 128;

    if (tid < HH) { ssum[tid] = 0.f; ssq[tid] = 0.f; }
    if (BN_IN) {
        if (tid < HH) {
            float s = instats[tid], q = instats[HH + tid];
            float m = s * (1.f / NN);
            float var = q * (1.f / NN) - m * m;
            smu[tid] = m;
            srs[tid] = rsqrtf(var + BN_EPS);
        }
    }

    // stage W -> smem (tf32 rounded)
    const float4* W4 = (const float4*)W;
#pragma unroll
    for (int i = 0; i < 16; i++) {
        int f = tid + i * 256;             // 0..4095
        int k = f >> 5, c = f & 31;
        float4 w = W4[k * 32 + c];
        uint32_t* dst = Ws + k * 132 + c * 4;
        dst[0] = f2tf32(w.x); dst[1] = f2tf32(w.y);
        dst[2] = f2tf32(w.z); dst[3] = f2tf32(w.w);
    }
    if (BN_IN) __syncthreads();   // smu/srs ready before loadA

    const float4* A4 = (const float4*)A;

    auto loadA = [&](int kt, int buf) {
        uint32_t* dstb = As + buf * 4608;
#pragma unroll
        for (int i = 0; i < 4; i++) {
            int f = tid + i * 256;         // 0..1023
            int r = f >> 3, c8 = f & 7;
            int gcol = kt + c8 * 4;
            float4 v = make_float4(0.f, 0.f, 0.f, 0.f);
            int gr = row0 + r;
            if (gr < NN) v = A4[(size_t)gr * 32 + (kt >> 2) + c8];
            if (BN_IN) {
                v.x = fmaxf((v.x - smu[gcol + 0]) * srs[gcol + 0] * bng[gcol + 0] + bnb[gcol + 0], 0.f);
                v.y = fmaxf((v.y - smu[gcol + 1]) * srs[gcol + 1] * bng[gcol + 1] + bnb[gcol + 1], 0.f);
                v.z = fmaxf((v.z - smu[gcol + 2]) * srs[gcol + 2] * bng[gcol + 2] + bnb[gcol + 2], 0.f);
                v.w = fmaxf((v.w - smu[gcol + 3]) * srs[gcol + 3] * bng[gcol + 3] + bnb[gcol + 3], 0.f);
            }
            uint32_t* dst = dstb + r * 36 + c8 * 4;
            dst[0] = f2tf32(v.x); dst[1] = f2tf32(v.y);
            dst[2] = f2tf32(v.z); dst[3] = f2tf32(v.w);
        }
    };

    float acc[2][8][4];
#pragma unroll
    for (int mi = 0; mi < 2; mi++)
#pragma unroll
        for (int ni = 0; ni < 8; ni++)
#pragma unroll
            for (int r = 0; r < 4; r++) acc[mi][ni][r] = 0.f;

    loadA(0, 0);
    __syncthreads();

#pragma unroll
    for (int ch = 0; ch < 4; ch++) {
        if (ch < 3) loadA((ch + 1) * 32, (ch + 1) & 1);
        uint32_t* Ab = As + (ch & 1) * 4608;
        int ktg = ch * 32;
#pragma unroll
        for (int ks = 0; ks < 4; ks++) {
            int kl = ks * 8 + (lane & 3);
            uint32_t a[2][4];
#pragma unroll
            for (int mi = 0; mi < 2; mi++) {
                int r = m0 + mi * 16 + (lane >> 2);
                a[mi][0] = Ab[r * 36 + kl];
                a[mi][1] = Ab[(r + 8) * 36 + kl];
                a[mi][2] = Ab[r * 36 + kl + 4];
                a[mi][3] = Ab[(r + 8) * 36 + kl + 4];
            }
            int kg = ktg + ks * 8 + (lane & 3);
            uint32_t b[8][2];
#pragma unroll
            for (int ni = 0; ni < 8; ni++) {
                int nc = n0 + ni * 8 + (lane >> 2);
                b[ni][0] = Ws[kg * 132 + nc];
                b[ni][1] = Ws[(kg + 4) * 132 + nc];
            }
#pragma unroll
            for (int mi = 0; mi < 2; mi++)
#pragma unroll
                for (int ni = 0; ni < 8; ni++)
                    mma_tf32(acc[mi][ni][0], acc[mi][ni][1], acc[mi][ni][2], acc[mi][ni][3],
                             a[mi][0], a[mi][1], a[mi][2], a[mi][3],
                             b[ni][0], b[ni][1]);
        }
        __syncthreads();
    }

    // epilogue: bias + store + per-channel stats
    float psum[16], psq[16];
#pragma unroll
    for (int i = 0; i < 16; i++) { psum[i] = 0.f; psq[i] = 0.f; }

#pragma unroll
    for (int ni = 0; ni < 8; ni++) {
        int col = n0 + ni * 8 + 2 * (lane & 3);
        float b0v = bias[col], b1v = bias[col + 1];
#pragma unroll
        for (int mi = 0; mi < 2; mi++) {
            int r = row0 + m0 + mi * 16 + (lane >> 2);
            float v0 = acc[mi][ni][0] + b0v;
            float v1 = acc[mi][ni][1] + b1v;
            float v2 = acc[mi][ni][2] + b0v;
            float v3 = acc[mi][ni][3] + b1v;
            if (r < NN) {
                float2 st0 = make_float2(v0, v1);
                *(float2*)(out + (size_t)r * HH + col) = st0;
                psum[ni * 2]     += v0;  psq[ni * 2]     += v0 * v0;
                psum[ni * 2 + 1] += v1;  psq[ni * 2 + 1] += v1 * v1;
            }
            if (r + 8 < NN) {
                float2 st1 = make_float2(v2, v3);
                *(float2*)(out + (size_t)(r + 8) * HH + col) = st1;
                psum[ni * 2]     += v2;  psq[ni * 2]     += v2 * v2;
                psum[ni * 2 + 1] += v3;  psq[ni * 2 + 1] += v3 * v3;
            }
        }
    }

    // reduce across the 8 lanes sharing the same (lane & 3)
#pragma unroll
    for (int mask = 4; mask <= 16; mask <<= 1) {
#pragma unroll
        for (int i = 0; i < 16; i++) {
            psum[i] += __shfl_xor_sync(0xffffffff, psum[i], mask);
            psq[i]  += __shfl_xor_sync(0xffffffff, psq[i], mask);
        }
    }
    if (lane < 4) {
#pragma unroll
        for (int i = 0; i < 16; i++) {
            int col = n0 + 8 * (i >> 1) + 2 * lane + (i & 1);
            atomicAdd(&ssum[col], psum[i]);
            atomicAdd(&ssq[col], psq[i]);
        }
    }
    __syncthreads();
    if (tid < HH) {
        atomicAdd(&outstats[tid], ssum[tid]);
        atomicAdd(&outstats[HH + tid], ssq[tid]);
    }
}

// per-graph pooled sum of relu(bn2(d_h)) into d_pool[g][layer*128 + c]
__global__ void k_pool(int layer, const float* __restrict__ g2, const float* __restrict__ bt2,
                       const float* __restrict__ stats) {
    int g = blockIdx.x;
    int c = threadIdx.x;   // 128
    float s0 = stats[c], q0 = stats[HH + c];
    float m = s0 * (1.f / NN);
    float var = q0 * (1.f / NN) - m * m;
    float rs_ = rsqrtf(var + BN_EPS);
    float sc = rs_ * g2[c];
    float sh = bt2[c] - m * sc;
    int s = d_start[g], e = d_start[g + 1];
    float a0 = 0.f, a1 = 0.f, a2 = 0.f, a3 = 0.f;
    float a4 = 0.f, a5 = 0.f, a6 = 0.f, a7 = 0.f;
    int n = s;
    for (; n + 8 <= e; n += 8) {
        a0 += fmaxf(fmaf(d_h[(size_t)(n + 0) * HH + c], sc, sh), 0.f);
        a1 += fmaxf(fmaf(d_h[(size_t)(n + 1) * HH + c], sc, sh), 0.f);
        a2 += fmaxf(fmaf(d_h[(size_t)(n + 2) * HH + c], sc, sh), 0.f);
        a3 += fmaxf(fmaf(d_h[(size_t)(n + 3) * HH + c], sc, sh), 0.f);
        a4 += fmaxf(fmaf(d_h[(size_t)(n + 4) * HH + c], sc, sh), 0.f);
        a5 += fmaxf(fmaf(d_h[(size_t)(n + 5) * HH + c], sc, sh), 0.f);
        a6 += fmaxf(fmaf(d_h[(size_t)(n + 6) * HH + c], sc, sh), 0.f);
        a7 += fmaxf(fmaf(d_h[(size_t)(n + 7) * HH + c], sc, sh), 0.f);
    }
    for (; n < e; ++n) a0 += fmaxf(fmaf(d_h[(size_t)n * HH + c], sc, sh), 0.f);
    d_pool[(size_t)g * (LL * HH) + layer * HH + c] =
        ((a0 + a1) + (a2 + a3)) + ((a4 + a5) + (a6 + a7));
}

// out[g] = relu(pool[g] @ fc1 + b1) @ fc2 + b2
__global__ void k_head(const float* __restrict__ fc1w, const float* __restrict__ fc1b,
                       const float* __restrict__ fc2w, const float* __restrict__ fc2b,
                       float* __restrict__ out) {
    __shared__ float sp[LL * HH];
    __shared__ float t1[HH];
    int g = blockIdx.x, t = threadIdx.x;   // 128 threads
    for (int k = t; k < LL * HH; k += HH) sp[k] = d_pool[(size_t)g * (LL * HH) + k];
    __syncthreads();
    float acc = fc1b[t];
#pragma unroll 8
    for (int k = 0; k < LL * HH; k++) acc += sp[k] * fc1w[(size_t)k * HH + t];
    t1[t] = fmaxf(acc, 0.f);
    __syncthreads();
    if (t < CC) {
        float a = fc2b[t];
#pragma unroll 8
        for (int j = 0; j < HH; j++) a += t1[j] * fc2w[j * CC + t];
        out[g * CC + t] = a;
    }
}

extern "C" void kernel_launch(void* const* d_in, const int* in_sizes, int n_in,
                              void* d_out, int out_size) {
    const float* x     = (const float*)d_in[0];
    const int*   ei    = (const int*)d_in[1];
    const int*   batch = (const int*)d_in[2];
    const float* W1    = (const float*)d_in[3];
    const float* b1    = (const float*)d_in[4];
    const float* g1    = (const float*)d_in[5];
    const float* bt1   = (const float*)d_in[6];
    const float* W2    = (const float*)d_in[7];
    const float* b2    = (const float*)d_in[8];
    const float* g2    = (const float*)d_in[9];
    const float* bt2   = (const float*)d_in[10];
    const float* eps   = (const float*)d_in[11];
    const float* fc1w  = (const float*)d_in[12];
    const float* fc1b  = (const float*)d_in[13];
    const float* fc2w  = (const float*)d_in[14];
    const float* fc2b  = (const float*)d_in[15];
    float* out = (float*)d_out;

    const int* src = ei;
    const int* dst = ei + EE;

    float *hbuf, *zbuf, *ybuf, *stA, *stB;
    cudaGetSymbolAddress((void**)&hbuf, d_h);
    cudaGetSymbolAddress((void**)&zbuf, d_z);
    cudaGetSymbolAddress((void**)&ybuf, d_y);
    cudaGetSymbolAddress((void**)&stA, d_stA);
    cudaGetSymbolAddress((void**)&stB, d_stB);

    cudaFuncSetAttribute(k_gemm_tc<false>, cudaFuncAttributeMaxDynamicSharedMemorySize, GEMM_SMEM_BYTES);
    cudaFuncSetAttribute(k_gemm_tc<true>,  cudaFuncAttributeMaxDynamicSharedMemorySize, GEMM_SMEM_BYTES);

    const int gemm_blocks = (NN + 127) / 128;                // 391
    const int agg_blocks  = (NN * 32 + 255) / 256;           // warp per node
    const int edge4_blocks = (EE / 4 + 255) / 256;

    // ---- per-replay: bounds + zero + CSR build ----
    k_init<<<SCAN_BLOCKS, 256>>>(batch);
    k_hist<<<edge4_blocks, 256>>>(dst);
    k_scan1<<<SCAN_BLOCKS, 256>>>();
    k_scan2<<<1, 256>>>();
    k_scan3<<<SCAN_BLOCKS, 256>>>();
    k_fill<<<edge4_blocks, 256>>>(src, dst);

    for (int i = 0; i < LL; i++) {
        float* stAi = stA + (size_t)i * 2 * HH;
        float* stBi = stB + (size_t)i * 2 * HH;
        if (i == 0) {
            k_agg<false><<<agg_blocks, 256>>>(x, eps, i, nullptr, nullptr, nullptr);
        } else {
            k_agg<true><<<agg_blocks, 256>>>(hbuf, eps, i,
                                             g2 + (i - 1) * HH, bt2 + (i - 1) * HH,
                                             stB + (size_t)(i - 1) * 2 * HH);
        }
        // y = z @ W1[i] + b1[i]; raw stats -> stA[i]
        k_gemm_tc<false><<<gemm_blocks, 256, GEMM_SMEM_BYTES>>>(
            zbuf, W1 + (size_t)i * HH * HH, b1 + i * HH, nullptr, nullptr, nullptr,
            ybuf, stAi);
        // z2 = relu(bn1(y)) @ W2[i] + b2[i]; raw stats -> stB[i] (z2 stays pre-BN in d_h)
        k_gemm_tc<true><<<gemm_blocks, 256, GEMM_SMEM_BYTES>>>(
            ybuf, W2 + (size_t)i * HH * HH, b2 + i * HH, g1 + i * HH, bt1 + i * HH, stAi,
            hbuf, stBi);
        k_pool<<<GG, HH>>>(i, g2 + i * HH, bt2 + i * HH, stBi);
    }

    k_head<<<GG, HH>>>(fc1w, fc1b, fc2w, fc2b, out);
}

// round 8
// speedup vs baseline: 3.5960x; 1.0274x over previous
#include <cuda_runtime.h>
#include <cuda_bf16.h>
#include <cstdint>

#define NN 50000
#define EE 600000
#define HH 128
#define LL 4
#define GG 256
#define CC 10
#define BN_EPS 1e-5f

// -------- device scratch (no allocations allowed) --------
__device__ float d_hl[LL][NN * HH]; // pre-BN z2 per layer
__device__ float d_z[NN * HH];      // agg output
__device__ float d_y[NN * HH];      // GEMM1 output
__device__ float d_pool[GG * LL * HH];
__device__ float d_stA[LL][2 * HH]; // raw per-layer stats: [0:128) sum, [128:256) sumsq
__device__ float d_stB[LL][2 * HH];
__device__ int   d_start[GG + 1];
// CSR (dst-sorted adjacency)
__device__ int   d_cnt[NN];
__device__ int   d_cur[NN];
__device__ int   d_rowptr[NN + 1];
__device__ int   d_col[EE];
__device__ int   d_bsum[256];
__device__ int   d_boff[256];

#define SCAN_BLOCKS ((NN + 255) / 256)   // 196

// -------- init: graph bounds + zero counters + zero stats (one kernel) --------
__global__ void k_init(const int* __restrict__ batch) {
    int n = blockIdx.x * blockDim.x + threadIdx.x;
    if (n < NN) {
        d_cnt[n] = 0;
        d_cur[n] = 0;
        int g = batch[n];
        if (n == 0) {
            for (int gg = 0; gg <= g; ++gg) d_start[gg] = 0;
        } else {
            int gp = batch[n - 1];
            for (int gg = gp + 1; gg <= g; ++gg) d_start[gg] = n;
        }
        if (n == NN - 1) {
            for (int gg = g + 1; gg <= GG; ++gg) d_start[gg] = NN;
        }
    }
    if (n < LL * 2 * HH) {
        ((float*)d_stA)[n] = 0.f;
        ((float*)d_stB)[n] = 0.f;
    }
}

// -------- CSR build (4 edges/thread) --------
__global__ void k_hist(const int* __restrict__ dst) {
    int i = blockIdx.x * blockDim.x + threadIdx.x;
    if (i >= EE / 4) return;
    int4 d = ((const int4*)dst)[i];
    atomicAdd(&d_cnt[d.x], 1);
    atomicAdd(&d_cnt[d.y], 1);
    atomicAdd(&d_cnt[d.z], 1);
    atomicAdd(&d_cnt[d.w], 1);
}

__global__ void k_scan1() {
    __shared__ int sp[256];
    int t = threadIdx.x;
    int i = blockIdx.x * 256 + t;
    int v = (i < NN) ? d_cnt[i] : 0;
    sp[t] = v;
    __syncthreads();
    for (int off = 128; off > 0; off >>= 1) {
        if (t < off) sp[t] += sp[t + off];
        __syncthreads();
    }
    if (t == 0) d_bsum[blockIdx.x] = sp[0];
}

__global__ void k_scan2() {
    __shared__ int sp[256];
    int t = threadIdx.x;
    int v = (t < SCAN_BLOCKS) ? d_bsum[t] : 0;
    sp[t] = v;
    __syncthreads();
    for (int off = 1; off < 256; off <<= 1) {
        int u = 0;
        if (t >= off) u = sp[t - off];
        __syncthreads();
        if (t >= off) sp[t] += u;
        __syncthreads();
    }
    d_boff[t] = sp[t] - v;   // exclusive
    if (t == 0) d_rowptr[NN] = EE;
}

__global__ void k_scan3() {
    __shared__ int sp[256];
    int t = threadIdx.x;
    int i = blockIdx.x * 256 + t;
    int v = (i < NN) ? d_cnt[i] : 0;
    sp[t] = v;
    __syncthreads();
    for (int off = 1; off < 256; off <<= 1) {
        int u = 0;
        if (t >= off) u = sp[t - off];
        __syncthreads();
        if (t >= off) sp[t] += u;
        __syncthreads();
    }
    if (i < NN) d_rowptr[i] = d_boff[blockIdx.x] + sp[t] - v;
}

__global__ void k_fill(const int* __restrict__ src, const int* __restrict__ dst) {
    int i = blockIdx.x * blockDim.x + threadIdx.x;
    if (i >= EE / 4) return;
    int4 d = ((const int4*)dst)[i];
    int4 s = ((const int4*)src)[i];
    int p;
    p = atomicAdd(&d_cur[d.x], 1); d_col[d_rowptr[d.x] + p] = s.x;
    p = atomicAdd(&d_cur[d.y], 1); d_col[d_rowptr[d.y] + p] = s.y;
    p = atomicAdd(&d_cur[d.z], 1); d_col[d_rowptr[d.z] + p] = s.z;
    p = atomicAdd(&d_cur[d.w], 1); d_col[d_rowptr[d.w] + p] = s.w;
}

// -------- gather aggregation with lazy BN on input --------
// z[n] = (1+eps)*f(h[n]) + sum_{s in adj(n)} f(h[s]),  f = relu(bn2) (NORM) or identity
// Always-8-wide predicated gather: clamped indices + masked accumulate keep full MLP.
template <bool NORM>
__global__ __launch_bounds__(256) void k_agg(const float* __restrict__ hin,
                                             const float* __restrict__ eps, int layer,
                                             const float* __restrict__ g2,
                                             const float* __restrict__ bt2,
                                             const float* __restrict__ statsPrev) {
    int t = blockIdx.x * blockDim.x + threadIdx.x;
    int n = t >> 5;
    int l = t & 31;
    if (n >= NN) return;

    float sc0 = 1.f, sc1 = 1.f, sc2 = 1.f, sc3 = 1.f;
    float sh0 = 0.f, sh1 = 0.f, sh2 = 0.f, sh3 = 0.f;
    if (NORM) {
        int c = l * 4;
#pragma unroll
        for (int j = 0; j < 4; j++) {
            float s = __ldg(&statsPrev[c + j]);
            float q = __ldg(&statsPrev[HH + c + j]);
            float m = s * (1.f / NN);
            float var = q * (1.f / NN) - m * m;
            float rs_ = rsqrtf(var + BN_EPS);
            float sc = rs_ * __ldg(&g2[c + j]);
            float sh = __ldg(&bt2[c + j]) - m * sc;
            if (j == 0) { sc0 = sc; sh0 = sh; }
            else if (j == 1) { sc1 = sc; sh1 = sh; }
            else if (j == 2) { sc2 = sc; sh2 = sh; }
            else { sc3 = sc; sh3 = sh; }
        }
    }

    const float4* h4 = (const float4*)hin;
    auto rd = [&](int node) -> float4 {
        float4 u = __ldg(&h4[(size_t)node * 32 + l]);
        if (NORM) {
            u.x = fmaxf(fmaf(u.x, sc0, sh0), 0.f);
            u.y = fmaxf(fmaf(u.y, sc1, sh1), 0.f);
            u.z = fmaxf(fmaf(u.z, sc2, sh2), 0.f);
            u.w = fmaxf(fmaf(u.w, sc3, sh3), 0.f);
        }
        return u;
    };

    float s = 1.f + __ldg(&eps[layer]);
    float4 v = rd(n);
    float ax = v.x * s, ay = v.y * s, az = v.z * s, aw = v.w * s;

    int p0 = d_rowptr[n], p1 = d_rowptr[n + 1];
    for (int p = p0; p < p1; p += 8) {
        int idx[8];
        float msk[8];
#pragma unroll
        for (int j = 0; j < 8; j++) {
            int pp = p + j;
            msk[j] = (pp < p1) ? 1.f : 0.f;
            idx[j] = __ldg(&d_col[pp < p1 ? pp : (p1 - 1)]);
        }
        float4 u[8];
#pragma unroll
        for (int j = 0; j < 8; j++) u[j] = rd(idx[j]);
#pragma unroll
        for (int j = 0; j < 8; j++) {
            ax = fmaf(msk[j], u[j].x, ax);
            ay = fmaf(msk[j], u[j].y, ay);
            az = fmaf(msk[j], u[j].z, az);
            aw = fmaf(msk[j], u[j].w, aw);
        }
    }
    ((float4*)d_z)[(size_t)n * 32 + l] = make_float4(ax, ay, az, aw);
}

// -------- TF32 tensor-core GEMM: out[N,128] = f(A)[N,128] @ W[128,128] + bias --------
#define GEMM_SMEM_WORDS 26624
#define GEMM_SMEM_BYTES (GEMM_SMEM_WORDS * 4)

__device__ __forceinline__ uint32_t f2tf32(float f) {
    uint32_t o;
    asm("cvt.rna.tf32.f32 %0, %1;" : "=r"(o) : "f"(f));
    return o;
}

__device__ __forceinline__ void mma_tf32(float& c0, float& c1, float& c2, float& c3,
                                         uint32_t a0, uint32_t a1, uint32_t a2, uint32_t a3,
                                         uint32_t b0, uint32_t b1) {
    asm volatile(
        "mma.sync.aligned.m16n8k8.row.col.f32.tf32.tf32.f32 "
        "{%0,%1,%2,%3}, {%4,%5,%6,%7}, {%8,%9}, {%0,%1,%2,%3};"
        : "+f"(c0), "+f"(c1), "+f"(c2), "+f"(c3)
        : "r"(a0), "r"(a1), "r"(a2), "r"(a3), "r"(b0), "r"(b1));
}

template <bool BN_IN>
__global__ __launch_bounds__(256) void k_gemm_tc(
    const float* __restrict__ A, const float* __restrict__ W,
    const float* __restrict__ bias,
    const float* __restrict__ bng, const float* __restrict__ bnb,
    const float* __restrict__ instats,   // raw sums (BN_IN only)
    float* __restrict__ out, float* __restrict__ outstats) {

    extern __shared__ uint32_t sm[];
    uint32_t* Ws = sm;                     // [128][132]
    uint32_t* As = sm + 16896;             // [2][128][36]
    float* ssum = (float*)(sm + 26112);
    float* ssq  = (float*)(sm + 26240);
    float* smu  = (float*)(sm + 26368);
    float* srs  = (float*)(sm + 26496);

    int tid = threadIdx.x;
    int lane = tid & 31;
    int warp = tid >> 5;
    int m0 = (warp >> 1) * 32;
    int n0 = (warp & 1) * 64;
    int row0 = blockIdx.x * 128;

    if (tid < HH) { ssum[tid] = 0.f; ssq[tid] = 0.f; }
    if (BN_IN) {
        if (tid < HH) {
            float s = instats[tid], q = instats[HH + tid];
            float m = s * (1.f / NN);
            float var = q * (1.f / NN) - m * m;
            smu[tid] = m;
            srs[tid] = rsqrtf(var + BN_EPS);
        }
    }

    const float4* W4 = (const float4*)W;
#pragma unroll
    for (int i = 0; i < 16; i++) {
        int f = tid + i * 256;
        int k = f >> 5, c = f & 31;
        float4 w = W4[k * 32 + c];
        uint32_t* dst = Ws + k * 132 + c * 4;
        dst[0] = f2tf32(w.x); dst[1] = f2tf32(w.y);
        dst[2] = f2tf32(w.z); dst[3] = f2tf32(w.w);
    }
    if (BN_IN) __syncthreads();

    const float4* A4 = (const float4*)A;

    auto loadA = [&](int kt, int buf) {
        uint32_t* dstb = As + buf * 4608;
#pragma unroll
        for (int i = 0; i < 4; i++) {
            int f = tid + i * 256;
            int r = f >> 3, c8 = f & 7;
            int gcol = kt + c8 * 4;
            float4 v = make_float4(0.f, 0.f, 0.f, 0.f);
            int gr = row0 + r;
            if (gr < NN) v = A4[(size_t)gr * 32 + (kt >> 2) + c8];
            if (BN_IN) {
                v.x = fmaxf((v.x - smu[gcol + 0]) * srs[gcol + 0] * bng[gcol + 0] + bnb[gcol + 0], 0.f);
                v.y = fmaxf((v.y - smu[gcol + 1]) * srs[gcol + 1] * bng[gcol + 1] + bnb[gcol + 1], 0.f);
                v.z = fmaxf((v.z - smu[gcol + 2]) * srs[gcol + 2] * bng[gcol + 2] + bnb[gcol + 2], 0.f);
                v.w = fmaxf((v.w - smu[gcol + 3]) * srs[gcol + 3] * bng[gcol + 3] + bnb[gcol + 3], 0.f);
            }
            uint32_t* dst = dstb + r * 36 + c8 * 4;
            dst[0] = f2tf32(v.x); dst[1] = f2tf32(v.y);
            dst[2] = f2tf32(v.z); dst[3] = f2tf32(v.w);
        }
    };

    float acc[2][8][4];
#pragma unroll
    for (int mi = 0; mi < 2; mi++)
#pragma unroll
        for (int ni = 0; ni < 8; ni++)
#pragma unroll
            for (int r = 0; r < 4; r++) acc[mi][ni][r] = 0.f;

    loadA(0, 0);
    __syncthreads();

#pragma unroll
    for (int ch = 0; ch < 4; ch++) {
        if (ch < 3) loadA((ch + 1) * 32, (ch + 1) & 1);
        uint32_t* Ab = As + (ch & 1) * 4608;
        int ktg = ch * 32;
#pragma unroll
        for (int ks = 0; ks < 4; ks++) {
            int kl = ks * 8 + (lane & 3);
            uint32_t a[2][4];
#pragma unroll
            for (int mi = 0; mi < 2; mi++) {
                int r = m0 + mi * 16 + (lane >> 2);
                a[mi][0] = Ab[r * 36 + kl];
                a[mi][1] = Ab[(r + 8) * 36 + kl];
                a[mi][2] = Ab[r * 36 + kl + 4];
                a[mi][3] = Ab[(r + 8) * 36 + kl + 4];
            }
            int kg = ktg + ks * 8 + (lane & 3);
            uint32_t b[8][2];
#pragma unroll
            for (int ni = 0; ni < 8; ni++) {
                int nc = n0 + ni * 8 + (lane >> 2);
                b[ni][0] = Ws[kg * 132 + nc];
                b[ni][1] = Ws[(kg + 4) * 132 + nc];
            }
#pragma unroll
            for (int mi = 0; mi < 2; mi++)
#pragma unroll
                for (int ni = 0; ni < 8; ni++)
                    mma_tf32(acc[mi][ni][0], acc[mi][ni][1], acc[mi][ni][2], acc[mi][ni][3],
                             a[mi][0], a[mi][1], a[mi][2], a[mi][3],
                             b[ni][0], b[ni][1]);
        }
        __syncthreads();
    }

    float psum[16], psq[16];
#pragma unroll
    for (int i = 0; i < 16; i++) { psum[i] = 0.f; psq[i] = 0.f; }

#pragma unroll
    for (int ni = 0; ni < 8; ni++) {
        int col = n0 + ni * 8 + 2 * (lane & 3);
        float b0v = bias[col], b1v = bias[col + 1];
#pragma unroll
        for (int mi = 0; mi < 2; mi++) {
            int r = row0 + m0 + mi * 16 + (lane >> 2);
            float v0 = acc[mi][ni][0] + b0v;
            float v1 = acc[mi][ni][1] + b1v;
            float v2 = acc[mi][ni][2] + b0v;
            float v3 = acc[mi][ni][3] + b1v;
            if (r < NN) {
                *(float2*)(out + (size_t)r * HH + col) = make_float2(v0, v1);
                psum[ni * 2]     += v0;  psq[ni * 2]     += v0 * v0;
                psum[ni * 2 + 1] += v1;  psq[ni * 2 + 1] += v1 * v1;
            }
            if (r + 8 < NN) {
                *(float2*)(out + (size_t)(r + 8) * HH + col) = make_float2(v2, v3);
                psum[ni * 2]     += v2;  psq[ni * 2]     += v2 * v2;
                psum[ni * 2 + 1] += v3;  psq[ni * 2 + 1] += v3 * v3;
            }
        }
    }

#pragma unroll
    for (int mask = 4; mask <= 16; mask <<= 1) {
#pragma unroll
        for (int i = 0; i < 16; i++) {
            psum[i] += __shfl_xor_sync(0xffffffff, psum[i], mask);
            psq[i]  += __shfl_xor_sync(0xffffffff, psq[i], mask);
        }
    }
    if (lane < 4) {
#pragma unroll
        for (int i = 0; i < 16; i++) {
            int col = n0 + 8 * (i >> 1) + 2 * lane + (i & 1);
            atomicAdd(&ssum[col], psum[i]);
            atomicAdd(&ssq[col], psq[i]);
        }
    }
    __syncthreads();
    if (tid < HH) {
        atomicAdd(&outstats[tid], ssum[tid]);
        atomicAdd(&outstats[HH + tid], ssq[tid]);
    }
}

// -------- deferred pooling: all layers at once --------
// grid (GG, LL); pooled sum of relu(bn2(d_hl[layer])) -> d_pool[g][layer*128+c]
__global__ void k_pool_all(const float* __restrict__ g2all, const float* __restrict__ bt2all) {
    int g = blockIdx.x;
    int layer = blockIdx.y;
    int c = threadIdx.x;   // 128
    const float* stats = d_stB[layer];
    float s0 = stats[c], q0 = stats[HH + c];
    float m = s0 * (1.f / NN);
    float var = q0 * (1.f / NN) - m * m;
    float rs_ = rsqrtf(var + BN_EPS);
    float sc = rs_ * g2all[layer * HH + c];
    float sh = bt2all[layer * HH + c] - m * sc;
    const float* h = d_hl[layer];
    int s = d_start[g], e = d_start[g + 1];
    float a0 = 0.f, a1 = 0.f, a2 = 0.f, a3 = 0.f;
    float a4 = 0.f, a5 = 0.f, a6 = 0.f, a7 = 0.f;
    int n = s;
    for (; n + 8 <= e; n += 8) {
        a0 += fmaxf(fmaf(h[(size_t)(n + 0) * HH + c], sc, sh), 0.f);
        a1 += fmaxf(fmaf(h[(size_t)(n + 1) * HH + c], sc, sh), 0.f);
        a2 += fmaxf(fmaf(h[(size_t)(n + 2) * HH + c], sc, sh), 0.f);
        a3 += fmaxf(fmaf(h[(size_t)(n + 3) * HH + c], sc, sh), 0.f);
        a4 += fmaxf(fmaf(h[(size_t)(n + 4) * HH + c], sc, sh), 0.f);
        a5 += fmaxf(fmaf(h[(size_t)(n + 5) * HH + c], sc, sh), 0.f);
        a6 += fmaxf(fmaf(h[(size_t)(n + 6) * HH + c], sc, sh), 0.f);
        a7 += fmaxf(fmaf(h[(size_t)(n + 7) * HH + c], sc, sh), 0.f);
    }
    for (; n < e; ++n) a0 += fmaxf(fmaf(h[(size_t)n * HH + c], sc, sh), 0.f);
    d_pool[(size_t)g * (LL * HH) + layer * HH + c] =
        ((a0 + a1) + (a2 + a3)) + ((a4 + a5) + (a6 + a7));
}

// out[g] = relu(pool[g] @ fc1 + b1) @ fc2 + b2
__global__ void k_head(const float* __restrict__ fc1w, const float* __restrict__ fc1b,
                       const float* __restrict__ fc2w, const float* __restrict__ fc2b,
                       float* __restrict__ out) {
    __shared__ float sp[LL * HH];
    __shared__ float t1[HH];
    int g = blockIdx.x, t = threadIdx.x;   // 128 threads
    for (int k = t; k < LL * HH; k += HH) sp[k] = d_pool[(size_t)g * (LL * HH) + k];
    __syncthreads();
    float acc = fc1b[t];
#pragma unroll 8
    for (int k = 0; k < LL * HH; k++) acc += sp[k] * fc1w[(size_t)k * HH + t];
    t1[t] = fmaxf(acc, 0.f);
    __syncthreads();
    if (t < CC) {
        float a = fc2b[t];
#pragma unroll 8
        for (int j = 0; j < HH; j++) a += t1[j] * fc2w[j * CC + t];
        out[g * CC + t] = a;
    }
}

extern "C" void kernel_launch(void* const* d_in, const int* in_sizes, int n_in,
                              void* d_out, int out_size) {
    const float* x     = (const float*)d_in[0];
    const int*   ei    = (const int*)d_in[1];
    const int*   batch = (const int*)d_in[2];
    const float* W1    = (const float*)d_in[3];
    const float* b1    = (const float*)d_in[4];
    const float* g1    = (const float*)d_in[5];
    const float* bt1   = (const float*)d_in[6];
    const float* W2    = (const float*)d_in[7];
    const float* b2    = (const float*)d_in[8];
    const float* g2    = (const float*)d_in[9];
    const float* bt2   = (const float*)d_in[10];
    const float* eps   = (const float*)d_in[11];
    const float* fc1w  = (const float*)d_in[12];
    const float* fc1b  = (const float*)d_in[13];
    const float* fc2w  = (const float*)d_in[14];
    const float* fc2b  = (const float*)d_in[15];
    float* out = (float*)d_out;

    const int* src = ei;
    const int* dst = ei + EE;

    float *hl, *zbuf, *ybuf, *stA, *stB;
    cudaGetSymbolAddress((void**)&hl, d_hl);
    cudaGetSymbolAddress((void**)&zbuf, d_z);
    cudaGetSymbolAddress((void**)&ybuf, d_y);
    cudaGetSymbolAddress((void**)&stA, d_stA);
    cudaGetSymbolAddress((void**)&stB, d_stB);

    cudaFuncSetAttribute(k_gemm_tc<false>, cudaFuncAttributeMaxDynamicSharedMemorySize, GEMM_SMEM_BYTES);
    cudaFuncSetAttribute(k_gemm_tc<true>,  cudaFuncAttributeMaxDynamicSharedMemorySize, GEMM_SMEM_BYTES);

    const int gemm_blocks = (NN + 127) / 128;                // 391
    const int agg_blocks  = (NN * 32 + 255) / 256;           // warp per node
    const int edge4_blocks = (EE / 4 + 255) / 256;

    // ---- per-replay: bounds + zero + CSR build ----
    k_init<<<SCAN_BLOCKS, 256>>>(batch);
    k_hist<<<edge4_blocks, 256>>>(dst);
    k_scan1<<<SCAN_BLOCKS, 256>>>();
    k_scan2<<<1, 256>>>();
    k_scan3<<<SCAN_BLOCKS, 256>>>();
    k_fill<<<edge4_blocks, 256>>>(src, dst);

    for (int i = 0; i < LL; i++) {
        float* stAi = stA + (size_t)i * 2 * HH;
        float* stBi = stB + (size_t)i * 2 * HH;
        float* hout = hl + (size_t)i * NN * HH;
        if (i == 0) {
            k_agg<false><<<agg_blocks, 256>>>(x, eps, i, nullptr, nullptr, nullptr);
        } else {
            k_agg<true><<<agg_blocks, 256>>>(hl + (size_t)(i - 1) * NN * HH, eps, i,
                                             g2 + (i - 1) * HH, bt2 + (i - 1) * HH,
                                             stB + (size_t)(i - 1) * 2 * HH);
        }
        // y = z @ W1[i] + b1[i]; raw stats -> stA[i]
        k_gemm_tc<false><<<gemm_blocks, 256, GEMM_SMEM_BYTES>>>(
            zbuf, W1 + (size_t)i * HH * HH, b1 + i * HH, nullptr, nullptr, nullptr,
            ybuf, stAi);
        // z2 = relu(bn1(y)) @ W2[i] + b2[i]; raw stats -> stB[i] (pre-BN z2 -> d_hl[i])
        k_gemm_tc<true><<<gemm_blocks, 256, GEMM_SMEM_BYTES>>>(
            ybuf, W2 + (size_t)i * HH * HH, b2 + i * HH, g1 + i * HH, bt1 + i * HH, stAi,
            hout, stBi);
    }

    dim3 pool_grid(GG, LL);
    k_pool_all<<<pool_grid, HH>>>(g2, bt2);
    k_head<<<GG, HH>>>(fc1w, fc1b, fc2w, fc2b, out);
}

// round 9
// speedup vs baseline: 3.7471x; 1.0420x over previous
#include <cuda_runtime.h>
#include <cuda_bf16.h>
#include <cuda_fp16.h>
#include <cstdint>

#define NN 50000
#define EE 600000
#define HH 128
#define LL 4
#define GG 256
#define CC 10
#define BN_EPS 1e-5f

// -------- device scratch (no allocations allowed) --------
__device__ __half d_hl[LL][NN * HH]; // pre-BN z2 per layer (fp16 storage)
__device__ float d_z[NN * HH];       // agg output
__device__ float d_y[NN * HH];       // GEMM1 output
__device__ float d_pool[GG * LL * HH];
__device__ float d_stA[LL][2 * HH];  // raw per-layer stats: [0:128) sum, [128:256) sumsq
__device__ float d_stB[LL][2 * HH];
__device__ int   d_start[GG + 1];
// CSR (dst-sorted adjacency)
__device__ int   d_cnt[NN];
__device__ int   d_cur[NN];
__device__ int   d_rowptr[NN + 1];
__device__ int   d_col[EE];
__device__ int   d_bsum[256];
__device__ int   d_boff[256];

#define SCAN_BLOCKS ((NN + 255) / 256)   // 196

// -------- init: graph bounds + zero counters + zero stats (one kernel) --------
__global__ void k_init(const int* __restrict__ batch) {
    int n = blockIdx.x * blockDim.x + threadIdx.x;
    if (n < NN) {
        d_cnt[n] = 0;
        d_cur[n] = 0;
        int g = batch[n];
        if (n == 0) {
            for (int gg = 0; gg <= g; ++gg) d_start[gg] = 0;
        } else {
            int gp = batch[n - 1];
            for (int gg = gp + 1; gg <= g; ++gg) d_start[gg] = n;
        }
        if (n == NN - 1) {
            for (int gg = g + 1; gg <= GG; ++gg) d_start[gg] = NN;
        }
    }
    if (n < LL * 2 * HH) {
        ((float*)d_stA)[n] = 0.f;
        ((float*)d_stB)[n] = 0.f;
    }
}

// -------- CSR build (4 edges/thread) --------
__global__ void k_hist(const int* __restrict__ dst) {
    int i = blockIdx.x * blockDim.x + threadIdx.x;
    if (i >= EE / 4) return;
    int4 d = ((const int4*)dst)[i];
    atomicAdd(&d_cnt[d.x], 1);
    atomicAdd(&d_cnt[d.y], 1);
    atomicAdd(&d_cnt[d.z], 1);
    atomicAdd(&d_cnt[d.w], 1);
}

__global__ void k_scan1() {
    __shared__ int sp[256];
    int t = threadIdx.x;
    int i = blockIdx.x * 256 + t;
    int v = (i < NN) ? d_cnt[i] : 0;
    sp[t] = v;
    __syncthreads();
    for (int off = 128; off > 0; off >>= 1) {
        if (t < off) sp[t] += sp[t + off];
        __syncthreads();
    }
    if (t == 0) d_bsum[blockIdx.x] = sp[0];
}

__global__ void k_scan2() {
    __shared__ int sp[256];
    int t = threadIdx.x;
    int v = (t < SCAN_BLOCKS) ? d_bsum[t] : 0;
    sp[t] = v;
    __syncthreads();
    for (int off = 1; off < 256; off <<= 1) {
        int u = 0;
        if (t >= off) u = sp[t - off];
        __syncthreads();
        if (t >= off) sp[t] += u;
        __syncthreads();
    }
    d_boff[t] = sp[t] - v;   // exclusive
    if (t == 0) d_rowptr[NN] = EE;
}

__global__ void k_scan3() {
    __shared__ int sp[256];
    int t = threadIdx.x;
    int i = blockIdx.x * 256 + t;
    int v = (i < NN) ? d_cnt[i] : 0;
    sp[t] = v;
    __syncthreads();
    for (int off = 1; off < 256; off <<= 1) {
        int u = 0;
        if (t >= off) u = sp[t - off];
        __syncthreads();
        if (t >= off) sp[t] += u;
        __syncthreads();
    }
    if (i < NN) d_rowptr[i] = d_boff[blockIdx.x] + sp[t] - v;
}

__global__ void k_fill(const int* __restrict__ src, const int* __restrict__ dst) {
    int i = blockIdx.x * blockDim.x + threadIdx.x;
    if (i >= EE / 4) return;
    int4 d = ((const int4*)dst)[i];
    int4 s = ((const int4*)src)[i];
    int p;
    p = atomicAdd(&d_cur[d.x], 1); d_col[d_rowptr[d.x] + p] = s.x;
    p = atomicAdd(&d_cur[d.y], 1); d_col[d_rowptr[d.y] + p] = s.y;
    p = atomicAdd(&d_cur[d.z], 1); d_col[d_rowptr[d.z] + p] = s.z;
    p = atomicAdd(&d_cur[d.w], 1); d_col[d_rowptr[d.w] + p] = s.w;
}

// -------- layer-0 aggregation: fp32 input x, no BN --------
__global__ __launch_bounds__(256) void k_agg_f32(const float* __restrict__ hin,
                                                 const float* __restrict__ eps) {
    int t = blockIdx.x * blockDim.x + threadIdx.x;
    int n = t >> 5;
    int l = t & 31;
    if (n >= NN) return;

    const float4* h4 = (const float4*)hin;
    float s = 1.f + __ldg(&eps[0]);
    float4 v = __ldg(&h4[(size_t)n * 32 + l]);
    float ax = v.x * s, ay = v.y * s, az = v.z * s, aw = v.w * s;

    int p0 = d_rowptr[n], p1 = d_rowptr[n + 1];
    for (int p = p0; p < p1; p += 8) {
        int idx[8];
        float msk[8];
#pragma unroll
        for (int j = 0; j < 8; j++) {
            int pp = p + j;
            msk[j] = (pp < p1) ? 1.f : 0.f;
            idx[j] = __ldg(&d_col[pp < p1 ? pp : (p1 - 1)]);
        }
        float4 u[8];
#pragma unroll
        for (int j = 0; j < 8; j++) u[j] = __ldg(&h4[(size_t)idx[j] * 32 + l]);
#pragma unroll
        for (int j = 0; j < 8; j++) {
            ax = fmaf(msk[j], u[j].x, ax);
            ay = fmaf(msk[j], u[j].y, ay);
            az = fmaf(msk[j], u[j].z, az);
            aw = fmaf(msk[j], u[j].w, aw);
        }
    }
    ((float4*)d_z)[(size_t)n * 32 + l] = make_float4(ax, ay, az, aw);
}

// -------- layers 1+: fp16 input with lazy BN+relu --------
// z[n] = (1+eps)*f(h[n]) + sum f(h[s]),  f = relu(h*sc+sh)
__global__ __launch_bounds__(256) void k_agg_f16(const __half* __restrict__ hin,
                                                 const float* __restrict__ eps, int layer,
                                                 const float* __restrict__ g2,
                                                 const float* __restrict__ bt2,
                                                 const float* __restrict__ statsPrev) {
    int t = blockIdx.x * blockDim.x + threadIdx.x;
    int n = t >> 5;
    int l = t & 31;
    if (n >= NN) return;

    float sc0, sc1, sc2, sc3, sh0, sh1, sh2, sh3;
    {
        int c = l * 4;
        float scs[4], shs[4];
#pragma unroll
        for (int j = 0; j < 4; j++) {
            float s = __ldg(&statsPrev[c + j]);
            float q = __ldg(&statsPrev[HH + c + j]);
            float m = s * (1.f / NN);
            float var = q * (1.f / NN) - m * m;
            float rs_ = rsqrtf(var + BN_EPS);
            scs[j] = rs_ * __ldg(&g2[c + j]);
            shs[j] = __ldg(&bt2[c + j]) - m * scs[j];
        }
        sc0 = scs[0]; sc1 = scs[1]; sc2 = scs[2]; sc3 = scs[3];
        sh0 = shs[0]; sh1 = shs[1]; sh2 = shs[2]; sh3 = shs[3];
    }

    const float2* h2 = (const float2*)hin;  // 4 halves per float2; 32 per row
    auto rd = [&](int node) -> float4 {
        float2 raw = __ldg(&h2[(size_t)node * 32 + l]);
        __half2 p01 = *(__half2*)&raw.x;
        __half2 p23 = *(__half2*)&raw.y;
        float2 f01 = __half22float2(p01);
        float2 f23 = __half22float2(p23);
        float4 u;
        u.x = fmaxf(fmaf(f01.x, sc0, sh0), 0.f);
        u.y = fmaxf(fmaf(f01.y, sc1, sh1), 0.f);
        u.z = fmaxf(fmaf(f23.x, sc2, sh2), 0.f);
        u.w = fmaxf(fmaf(f23.y, sc3, sh3), 0.f);
        return u;
    };

    float s = 1.f + __ldg(&eps[layer]);
    float4 v = rd(n);
    float ax = v.x * s, ay = v.y * s, az = v.z * s, aw = v.w * s;

    int p0 = d_rowptr[n], p1 = d_rowptr[n + 1];
    for (int p = p0; p < p1; p += 8) {
        int idx[8];
        float msk[8];
#pragma unroll
        for (int j = 0; j < 8; j++) {
            int pp = p + j;
            msk[j] = (pp < p1) ? 1.f : 0.f;
            idx[j] = __ldg(&d_col[pp < p1 ? pp : (p1 - 1)]);
        }
        float4 u[8];
#pragma unroll
        for (int j = 0; j < 8; j++) u[j] = rd(idx[j]);
#pragma unroll
        for (int j = 0; j < 8; j++) {
            ax = fmaf(msk[j], u[j].x, ax);
            ay = fmaf(msk[j], u[j].y, ay);
            az = fmaf(msk[j], u[j].z, az);
            aw = fmaf(msk[j], u[j].w, aw);
        }
    }
    ((float4*)d_z)[(size_t)n * 32 + l] = make_float4(ax, ay, az, aw);
}

// -------- TF32 tensor-core GEMM --------
#define GEMM_SMEM_WORDS 26624
#define GEMM_SMEM_BYTES (GEMM_SMEM_WORDS * 4)

__device__ __forceinline__ uint32_t f2tf32(float f) {
    uint32_t o;
    asm("cvt.rna.tf32.f32 %0, %1;" : "=r"(o) : "f"(f));
    return o;
}

__device__ __forceinline__ void mma_tf32(float& c0, float& c1, float& c2, float& c3,
                                         uint32_t a0, uint32_t a1, uint32_t a2, uint32_t a3,
                                         uint32_t b0, uint32_t b1) {
    asm volatile(
        "mma.sync.aligned.m16n8k8.row.col.f32.tf32.tf32.f32 "
        "{%0,%1,%2,%3}, {%4,%5,%6,%7}, {%8,%9}, {%0,%1,%2,%3};"
        : "+f"(c0), "+f"(c1), "+f"(c2), "+f"(c3)
        : "r"(a0), "r"(a1), "r"(a2), "r"(a3), "r"(b0), "r"(b1));
}

// BN_IN: normalize A with instats+bng/bnb then relu. HALF_OUT: store __half output.
template <bool BN_IN, bool HALF_OUT>
__global__ __launch_bounds__(256) void k_gemm_tc(
    const float* __restrict__ A, const float* __restrict__ W,
    const float* __restrict__ bias,
    const float* __restrict__ bng, const float* __restrict__ bnb,
    const float* __restrict__ instats,
    void* __restrict__ outv, float* __restrict__ outstats) {

    extern __shared__ uint32_t sm[];
    uint32_t* Ws = sm;                     // [128][132]
    uint32_t* As = sm + 16896;             // [2][128][36]
    float* ssum = (float*)(sm + 26112);
    float* ssq  = (float*)(sm + 26240);
    float* smu  = (float*)(sm + 26368);
    float* srs  = (float*)(sm + 26496);

    int tid = threadIdx.x;
    int lane = tid & 31;
    int warp = tid >> 5;
    int m0 = (warp >> 1) * 32;
    int n0 = (warp & 1) * 64;
    int row0 = blockIdx.x * 128;

    if (tid < HH) { ssum[tid] = 0.f; ssq[tid] = 0.f; }
    if (BN_IN) {
        if (tid < HH) {
            float s = instats[tid], q = instats[HH + tid];
            float m = s * (1.f / NN);
            float var = q * (1.f / NN) - m * m;
            smu[tid] = m;
            srs[tid] = rsqrtf(var + BN_EPS);
        }
    }

    const float4* W4 = (const float4*)W;
#pragma unroll
    for (int i = 0; i < 16; i++) {
        int f = tid + i * 256;
        int k = f >> 5, c = f & 31;
        float4 w = W4[k * 32 + c];
        uint32_t* dst = Ws + k * 132 + c * 4;
        dst[0] = f2tf32(w.x); dst[1] = f2tf32(w.y);
        dst[2] = f2tf32(w.z); dst[3] = f2tf32(w.w);
    }
    if (BN_IN) __syncthreads();

    const float4* A4 = (const float4*)A;

    auto loadA = [&](int kt, int buf) {
        uint32_t* dstb = As + buf * 4608;
#pragma unroll
        for (int i = 0; i < 4; i++) {
            int f = tid + i * 256;
            int r = f >> 3, c8 = f & 7;
            int gcol = kt + c8 * 4;
            float4 v = make_float4(0.f, 0.f, 0.f, 0.f);
            int gr = row0 + r;
            if (gr < NN) v = A4[(size_t)gr * 32 + (kt >> 2) + c8];
            if (BN_IN) {
                v.x = fmaxf((v.x - smu[gcol + 0]) * srs[gcol + 0] * bng[gcol + 0] + bnb[gcol + 0], 0.f);
                v.y = fmaxf((v.y - smu[gcol + 1]) * srs[gcol + 1] * bng[gcol + 1] + bnb[gcol + 1], 0.f);
                v.z = fmaxf((v.z - smu[gcol + 2]) * srs[gcol + 2] * bng[gcol + 2] + bnb[gcol + 2], 0.f);
                v.w = fmaxf((v.w - smu[gcol + 3]) * srs[gcol + 3] * bng[gcol + 3] + bnb[gcol + 3], 0.f);
            }
            uint32_t* dst = dstb + r * 36 + c8 * 4;
            dst[0] = f2tf32(v.x); dst[1] = f2tf32(v.y);
            dst[2] = f2tf32(v.z); dst[3] = f2tf32(v.w);
        }
    };

    float acc[2][8][4];
#pragma unroll
    for (int mi = 0; mi < 2; mi++)
#pragma unroll
        for (int ni = 0; ni < 8; ni++)
#pragma unroll
            for (int r = 0; r < 4; r++) acc[mi][ni][r] = 0.f;

    loadA(0, 0);
    __syncthreads();

#pragma unroll
    for (int ch = 0; ch < 4; ch++) {
        if (ch < 3) loadA((ch + 1) * 32, (ch + 1) & 1);
        uint32_t* Ab = As + (ch & 1) * 4608;
        int ktg = ch * 32;
#pragma unroll
        for (int ks = 0; ks < 4; ks++) {
            int kl = ks * 8 + (lane & 3);
            uint32_t a[2][4];
#pragma unroll
            for (int mi = 0; mi < 2; mi++) {
                int r = m0 + mi * 16 + (lane >> 2);
                a[mi][0] = Ab[r * 36 + kl];
                a[mi][1] = Ab[(r + 8) * 36 + kl];
                a[mi][2] = Ab[r * 36 + kl + 4];
                a[mi][3] = Ab[(r + 8) * 36 + kl + 4];
            }
            int kg = ktg + ks * 8 + (lane & 3);
            uint32_t b[8][2];
#pragma unroll
            for (int ni = 0; ni < 8; ni++) {
                int nc = n0 + ni * 8 + (lane >> 2);
                b[ni][0] = Ws[kg * 132 + nc];
                b[ni][1] = Ws[(kg + 4) * 132 + nc];
            }
#pragma unroll
            for (int mi = 0; mi < 2; mi++)
#pragma unroll
                for (int ni = 0; ni < 8; ni++)
                    mma_tf32(acc[mi][ni][0], acc[mi][ni][1], acc[mi][ni][2], acc[mi][ni][3],
                             a[mi][0], a[mi][1], a[mi][2], a[mi][3],
                             b[ni][0], b[ni][1]);
        }
        __syncthreads();
    }

    float* outf = (float*)outv;
    __half* outh = (__half*)outv;

    float psum[16], psq[16];
#pragma unroll
    for (int i = 0; i < 16; i++) { psum[i] = 0.f; psq[i] = 0.f; }

#pragma unroll
    for (int ni = 0; ni < 8; ni++) {
        int col = n0 + ni * 8 + 2 * (lane & 3);
        float b0v = bias[col], b1v = bias[col + 1];
#pragma unroll
        for (int mi = 0; mi < 2; mi++) {
            int r = row0 + m0 + mi * 16 + (lane >> 2);
            float v0 = acc[mi][ni][0] + b0v;
            float v1 = acc[mi][ni][1] + b1v;
            float v2 = acc[mi][ni][2] + b0v;
            float v3 = acc[mi][ni][3] + b1v;
            if (r < NN) {
                if (HALF_OUT) {
                    *(__half2*)(outh + (size_t)r * HH + col) = __floats2half2_rn(v0, v1);
                } else {
                    *(float2*)(outf + (size_t)r * HH + col) = make_float2(v0, v1);
                }
                psum[ni * 2]     += v0;  psq[ni * 2]     += v0 * v0;
                psum[ni * 2 + 1] += v1;  psq[ni * 2 + 1] += v1 * v1;
            }
            if (r + 8 < NN) {
                if (HALF_OUT) {
                    *(__half2*)(outh + (size_t)(r + 8) * HH + col) = __floats2half2_rn(v2, v3);
                } else {
                    *(float2*)(outf + (size_t)(r + 8) * HH + col) = make_float2(v2, v3);
                }
                psum[ni * 2]     += v2;  psq[ni * 2]     += v2 * v2;
                psum[ni * 2 + 1] += v3;  psq[ni * 2 + 1] += v3 * v3;
            }
        }
    }

#pragma unroll
    for (int mask = 4; mask <= 16; mask <<= 1) {
#pragma unroll
        for (int i = 0; i < 16; i++) {
            psum[i] += __shfl_xor_sync(0xffffffff, psum[i], mask);
            psq[i]  += __shfl_xor_sync(0xffffffff, psq[i], mask);
        }
    }
    if (lane < 4) {
#pragma unroll
        for (int i = 0; i < 16; i++) {
            int col = n0 + 8 * (i >> 1) + 2 * lane + (i & 1);
            atomicAdd(&ssum[col], psum[i]);
            atomicAdd(&ssq[col], psq[i]);
        }
    }
    __syncthreads();
    if (tid < HH) {
        atomicAdd(&outstats[tid], ssum[tid]);
        atomicAdd(&outstats[HH + tid], ssq[tid]);
    }
}

// -------- deferred pooling: all layers at once (fp16 h) --------
__global__ void k_pool_all(const float* __restrict__ g2all, const float* __restrict__ bt2all) {
    int g = blockIdx.x;
    int layer = blockIdx.y;
    int c = threadIdx.x;   // 128
    const float* stats = d_stB[layer];
    float s0 = stats[c], q0 = stats[HH + c];
    float m = s0 * (1.f / NN);
    float var = q0 * (1.f / NN) - m * m;
    float rs_ = rsqrtf(var + BN_EPS);
    float sc = rs_ * g2all[layer * HH + c];
    float sh = bt2all[layer * HH + c] - m * sc;
    const __half* h = d_hl[layer];
    int s = d_start[g], e = d_start[g + 1];
    float a0 = 0.f, a1 = 0.f, a2 = 0.f, a3 = 0.f;
    float a4 = 0.f, a5 = 0.f, a6 = 0.f, a7 = 0.f;
    int n = s;
    for (; n + 8 <= e; n += 8) {
        a0 += fmaxf(fmaf(__half2float(h[(size_t)(n + 0) * HH + c]), sc, sh), 0.f);
        a1 += fmaxf(fmaf(__half2float(h[(size_t)(n + 1) * HH + c]), sc, sh), 0.f);
        a2 += fmaxf(fmaf(__half2float(h[(size_t)(n + 2) * HH + c]), sc, sh), 0.f);
        a3 += fmaxf(fmaf(__half2float(h[(size_t)(n + 3) * HH + c]), sc, sh), 0.f);
        a4 += fmaxf(fmaf(__half2float(h[(size_t)(n + 4) * HH + c]), sc, sh), 0.f);
        a5 += fmaxf(fmaf(__half2float(h[(size_t)(n + 5) * HH + c]), sc, sh), 0.f);
        a6 += fmaxf(fmaf(__half2float(h[(size_t)(n + 6) * HH + c]), sc, sh), 0.f);
        a7 += fmaxf(fmaf(__half2float(h[(size_t)(n + 7) * HH + c]), sc, sh), 0.f);
    }
    for (; n < e; ++n) a0 += fmaxf(fmaf(__half2float(h[(size_t)n * HH + c]), sc, sh), 0.f);
    d_pool[(size_t)g * (LL * HH) + layer * HH + c] =
        ((a0 + a1) + (a2 + a3)) + ((a4 + a5) + (a6 + a7));
}

// out[g] = relu(pool[g] @ fc1 + b1) @ fc2 + b2
__global__ void k_head(const float* __restrict__ fc1w, const float* __restrict__ fc1b,
                       const float* __restrict__ fc2w, const float* __restrict__ fc2b,
                       float* __restrict__ out) {
    __shared__ float sp[LL * HH];
    __shared__ float t1[HH];
    int g = blockIdx.x, t = threadIdx.x;   // 128 threads
    for (int k = t; k < LL * HH; k += HH) sp[k] = d_pool[(size_t)g * (LL * HH) + k];
    __syncthreads();
    float acc = fc1b[t];
#pragma unroll 8
    for (int k = 0; k < LL * HH; k++) acc += sp[k] * fc1w[(size_t)k * HH + t];
    t1[t] = fmaxf(acc, 0.f);
    __syncthreads();
    if (t < CC) {
        float a = fc2b[t];
#pragma unroll 8
        for (int j = 0; j < HH; j++) a += t1[j] * fc2w[j * CC + t];
        out[g * CC + t] = a;
    }
}

extern "C" void kernel_launch(void* const* d_in, const int* in_sizes, int n_in,
                              void* d_out, int out_size) {
    const float* x     = (const float*)d_in[0];
    const int*   ei    = (const int*)d_in[1];
    const int*   batch = (const int*)d_in[2];
    const float* W1    = (const float*)d_in[3];
    const float* b1    = (const float*)d_in[4];
    const float* g1    = (const float*)d_in[5];
    const float* bt1   = (const float*)d_in[6];
    const float* W2    = (const float*)d_in[7];
    const float* b2    = (const float*)d_in[8];
    const float* g2    = (const float*)d_in[9];
    const float* bt2   = (const float*)d_in[10];
    const float* eps   = (const float*)d_in[11];
    const float* fc1w  = (const float*)d_in[12];
    const float* fc1b  = (const float*)d_in[13];
    const float* fc2w  = (const float*)d_in[14];
    const float* fc2b  = (const float*)d_in[15];
    float* out = (float*)d_out;

    const int* src = ei;
    const int* dst = ei + EE;

    __half* hl;
    float *zbuf, *ybuf, *stA, *stB;
    cudaGetSymbolAddress((void**)&hl, d_hl);
    cudaGetSymbolAddress((void**)&zbuf, d_z);
    cudaGetSymbolAddress((void**)&ybuf, d_y);
    cudaGetSymbolAddress((void**)&stA, d_stA);
    cudaGetSymbolAddress((void**)&stB, d_stB);

    cudaFuncSetAttribute(k_gemm_tc<false, false>, cudaFuncAttributeMaxDynamicSharedMemorySize, GEMM_SMEM_BYTES);
    cudaFuncSetAttribute(k_gemm_tc<true, true>,   cudaFuncAttributeMaxDynamicSharedMemorySize, GEMM_SMEM_BYTES);

    const int gemm_blocks = (NN + 127) / 128;                // 391
    const int agg_blocks  = (NN * 32 + 255) / 256;           // warp per node
    const int edge4_blocks = (EE / 4 + 255) / 256;

    // ---- per-replay: bounds + zero + CSR build ----
    k_init<<<SCAN_BLOCKS, 256>>>(batch);
    k_hist<<<edge4_blocks, 256>>>(dst);
    k_scan1<<<SCAN_BLOCKS, 256>>>();
    k_scan2<<<1, 256>>>();
    k_scan3<<<SCAN_BLOCKS, 256>>>();
    k_fill<<<edge4_blocks, 256>>>(src, dst);

    for (int i = 0; i < LL; i++) {
        float* stAi = stA + (size_t)i * 2 * HH;
        float* stBi = stB + (size_t)i * 2 * HH;
        __half* hout = hl + (size_t)i * NN * HH;
        if (i == 0) {
            k_agg_f32<<<agg_blocks, 256>>>(x, eps);
        } else {
            k_agg_f16<<<agg_blocks, 256>>>(hl + (size_t)(i - 1) * NN * HH, eps, i,
                                           g2 + (i - 1) * HH, bt2 + (i - 1) * HH,
                                           stB + (size_t)(i - 1) * 2 * HH);
        }
        // y = z @ W1[i] + b1[i]; raw stats -> stA[i]
        k_gemm_tc<false, false><<<gemm_blocks, 256, GEMM_SMEM_BYTES>>>(
            zbuf, W1 + (size_t)i * HH * HH, b1 + i * HH, nullptr, nullptr, nullptr,
            ybuf, stAi);
        // z2 = relu(bn1(y)) @ W2[i] + b2[i]; raw stats -> stB[i] (pre-BN z2 -> d_hl[i] fp16)
        k_gemm_tc<true, true><<<gemm_blocks, 256, GEMM_SMEM_BYTES>>>(
            ybuf, W2 + (size_t)i * HH * HH, b2 + i * HH, g1 + i * HH, bt1 + i * HH, stAi,
            hout, stBi);
    }

    dim3 pool_grid(GG, LL);
    k_pool_all<<<pool_grid, HH>>>(g2, bt2);
    k_head<<<GG, HH>>>(fc1w, fc1b, fc2w, fc2b, out);
}